// round 10
// baseline (speedup 1.0000x reference)
#include <cuda_runtime.h>
#include <cuda_fp16.h>
#include <cstdint>

// Problem constants (match reference)
#define NMAX      50000
#define EMAX      800000
#define IN_DIM    256
#define H_DIM     128
#define OUT_DIM   64
#define K_STEPS   10
#define ALPHA_F   0.1f

// Scale schedule: every prop divides stored values by 4 (exact, folded into
// fp32 scale constants). x_k true = y_k * (16 * 4^k); H true = Hs * 16.
#define PSCALE    4.0f

// gather launch geometry: single wave on 152 SMs
#define GBLOCKS   608
#define GTHREADS  256
#define NWARPS    (GBLOCKS * (GTHREADS / 32))   // 4864

// -------- scratch (no allocation allowed -> device globals) --------
__device__ __half gX0[(size_t)NMAX * OUT_DIM];  // X @ (W1@W2)          (scale 1)
__device__ __half gP [(size_t)NMAX * OUT_DIM];  // (prop(X0)+c)/4       (scale 4)
__device__ __half gH [(size_t)NMAX * OUT_DIM];  // (prop(P)+b2)/16     (scale 16)
__device__ __half gA [(size_t)NMAX * OUT_DIM];  // ping  (scale 16*4^k)
__device__ __half gB [(size_t)NMAX * OUT_DIM];  // pong
__device__ float  gWc[IN_DIM * OUT_DIM];        // W1 @ W2  (256x64)
__device__ float  gC [OUT_DIM];                 // b1 @ W2
__device__ int    gIdxIs64;
// CSR scratch
__device__ int    gCount[NMAX];
__device__ int    gRowPtr[NMAX + 1];
__device__ int    gWp[NMAX];
__device__ int    gWarpStart[NWARPS + 1];
__device__ __align__(16) int2 gCsr[EMAX];       // (src, w-bits) sorted by dst

// ------------- dtype detection: int64 vs int32 edge_index -------------
__global__ void detect_idx_dtype(const void* __restrict__ ei, int N)
{
    const long long* p = (const long long*)ei;
    int ok = 1;
    for (int i = 0; i < 64; i++) {
        long long v = p[i];
        if (v < 0 || v >= N) { ok = 0; break; }
    }
    gIdxIs64 = ok;
}

// ------------- CSR build -------------
__global__ void hist_dst(const void* __restrict__ ei, int E)
{
    int t = blockIdx.x * blockDim.x + threadIdx.x;
#pragma unroll
    for (int u = 0; u < 2; u++) {
        int e = t * 2 + u;
        if (e >= E) return;
        int d;
        if (gIdxIs64) d = (int)((const long long*)ei)[E + e];
        else          d = ((const int*)ei)[E + e];
        atomicAdd(&gCount[d], 1);
    }
}

__global__ void scan_rowptr(int N, int E)
{
    __shared__ int sSum[1024];
    const int tid = threadIdx.x;
    const int chunk = (N + 1023) / 1024;
    const int lo = tid * chunk;
    const int hi = min(lo + chunk, N);

    int s = 0;
    for (int i = lo; i < hi; i++) s += gCount[i];
    sSum[tid] = s;
    __syncthreads();

    for (int off = 1; off < 1024; off <<= 1) {
        int v = (tid >= off) ? sSum[tid - off] : 0;
        __syncthreads();
        sSum[tid] += v;
        __syncthreads();
    }
    int run = (tid == 0) ? 0 : sSum[tid - 1];
    for (int i = lo; i < hi; i++) {
        gRowPtr[i] = run;
        gWp[i]     = run;
        run += gCount[i];
    }
    if (tid == 1023) gRowPtr[N] = E;
}

// edge-balanced warp partition: warpStart[w] = min{n : rowPtr[n] >= w*E/W}
__global__ void warp_partition(int N, int E)
{
    int w = blockIdx.x * blockDim.x + threadIdx.x;
    if (w > NWARPS) return;
    if (w == 0)       { gWarpStart[0] = 0; return; }
    if (w == NWARPS)  { gWarpStart[NWARPS] = N; return; }
    long long targ = (long long)w * E / NWARPS;
    int lo = 0, hi = N;
    while (lo < hi) {
        int mid = (lo + hi) >> 1;
        if ((long long)gRowPtr[mid] < targ) lo = mid + 1;
        else hi = mid;
    }
    gWarpStart[w] = lo;
}

__global__ void fill_csr(const void* __restrict__ ei, const float* __restrict__ ew, int E)
{
    int t = blockIdx.x * blockDim.x + threadIdx.x;
#pragma unroll
    for (int u = 0; u < 2; u++) {
        int e = t * 2 + u;
        if (e >= E) return;
        int s, d;
        if (gIdxIs64) {
            const long long* p = (const long long*)ei;
            s = (int)p[e];
            d = (int)p[E + e];
        } else {
            const int* p = (const int*)ei;
            s = p[e];
            d = p[E + e];
        }
        int pos = atomicAdd(&gWp[d], 1);
        gCsr[pos] = make_int2(s, __float_as_int(ew[e]));
    }
}

// ------------- tiny: Wc = W1 @ W2 (256x64), c = b1 @ W2 (64) -------------
__global__ void combine_weights(const float* __restrict__ W1,
                                const float* __restrict__ b1,
                                const float* __restrict__ W2)
{
    int idx = blockIdx.x * blockDim.x + threadIdx.x;
    if (idx < IN_DIM * OUT_DIM) {
        int i = idx >> 6, j = idx & 63;
        float s = 0.0f;
        const float* w1r = W1 + (size_t)i * H_DIM;
#pragma unroll 8
        for (int k = 0; k < H_DIM; k++)
            s += w1r[k] * W2[(size_t)k * OUT_DIM + j];
        gWc[idx] = s;
    } else if (idx < IN_DIM * OUT_DIM + OUT_DIM) {
        int j = idx - IN_DIM * OUT_DIM;
        float s = 0.0f;
#pragma unroll 8
        for (int k = 0; k < H_DIM; k++)
            s += b1[k] * W2[(size_t)k * OUT_DIM + j];
        gC[j] = s;
    }
}

// ---------------- SGEMM: Ch[M,N] = A @ B, fp16 output (R7-proven) ----------------
template<int BM, int BN, int BK, int TM, int TN>
__global__ void sgemm_h(int M, int N, int K,
                        const float* __restrict__ A,
                        const float* __restrict__ B,
                        __half* __restrict__ Ch)
{
    constexpr int THREADS = (BM / TM) * (BN / TN);
    __shared__ float As[BK][BM];
    __shared__ float Bs[BK][BN];

    const int tid = threadIdx.x;
    const int tc  = tid % (BN / TN);
    const int tr  = tid / (BN / TN);
    const int rowBase = blockIdx.x * BM;
    const int colBase = blockIdx.y * BN;

    float acc[TM][TN];
#pragma unroll
    for (int i = 0; i < TM; i++)
#pragma unroll
        for (int j = 0; j < TN; j++) acc[i][j] = 0.0f;

    constexpr int A_VECS = BM * BK / (THREADS * 4);
    constexpr int B_VECS = BK * BN / (THREADS * 4);

    for (int k0 = 0; k0 < K; k0 += BK) {
#pragma unroll
        for (int i = 0; i < A_VECS; i++) {
            int lin = (tid + i * THREADS) * 4;
            int r = lin / BK, c = lin % BK;
            int grow = rowBase + r;
            float4 v = make_float4(0.f, 0.f, 0.f, 0.f);
            if (grow < M)
                v = *reinterpret_cast<const float4*>(A + (size_t)grow * K + k0 + c);
            As[c + 0][r] = v.x;
            As[c + 1][r] = v.y;
            As[c + 2][r] = v.z;
            As[c + 3][r] = v.w;
        }
#pragma unroll
        for (int i = 0; i < B_VECS; i++) {
            int lin = (tid + i * THREADS) * 4;
            int r = lin / BN, c = lin % BN;
            *reinterpret_cast<float4*>(&Bs[r][c]) =
                *reinterpret_cast<const float4*>(B + (size_t)(k0 + r) * N + colBase + c);
        }
        __syncthreads();

#pragma unroll
        for (int k = 0; k < BK; k++) {
            float ra[TM], rb[TN];
#pragma unroll
            for (int i = 0; i < TM; i++) ra[i] = As[k][tr * TM + i];
#pragma unroll
            for (int j = 0; j < TN; j++) rb[j] = Bs[k][tc * TN + j];
#pragma unroll
            for (int i = 0; i < TM; i++)
#pragma unroll
                for (int j = 0; j < TN; j++) acc[i][j] += ra[i] * rb[j];
        }
        __syncthreads();
    }

#pragma unroll
    for (int i = 0; i < TM; i++) {
        int grow = rowBase + tr * TM + i;
        if (grow >= M) continue;
#pragma unroll
        for (int j = 0; j < TN; j += 2) {
            __half2 h = __floats2half2_rn(acc[i][j], acc[i][j + 1]);
            *reinterpret_cast<__half2*>(Ch + (size_t)grow * N + colBase + tc * TN + j) = h;
        }
    }
}

// ------------- CSR gather prop, DIM=64, fp16 x, edge-balanced warps -------------
// Each warp processes nodes [warpStart[w], warpStart[w+1]) — ~equal edge counts.
// out[n,:] = wscale*sum_e w_e*x[src_e,:] + ascale*addv[n,:] + bscale*bias[:]
// lane l owns half2 pair {2l, 2l+1}. fp32 accumulation.
template<bool HALF_OUT>
__global__ void __launch_bounds__(GTHREADS, 4)
gather64h(const __half2* __restrict__ x,
          void* __restrict__ outv,
          const __half2* __restrict__ addv,  // may be null
          const float* __restrict__ bias,    // fp32[64], may be null
          int N, float wscale, float ascale, float bscale)
{
    int w = (blockIdx.x * blockDim.x + threadIdx.x) >> 5;
    int lane = threadIdx.x & 31;

    int nBeg = gWarpStart[w];
    int nEnd = gWarpStart[w + 1];

    for (int n = nBeg; n < nEnd; n++) {
        int e   = gRowPtr[n];
        int end = gRowPtr[n + 1];

        float ax = 0.f, ay = 0.f;

        // peel one edge if start is odd (keeps int4 loads 16B-aligned)
        if ((e & 1) && e < end) {
            int2 s0 = __ldg(&gCsr[e]);
            float2 f0 = __half22float2(__ldg(x + (size_t)s0.x * 32 + lane));
            float w0 = __int_as_float(s0.y);
            ax = fmaf(w0, f0.x, ax); ay = fmaf(w0, f0.y, ay);
            e++;
        }

        // 8 edges per iteration: 4 int4 CSR loads + 8 row loads in flight
        for (; e + 7 < end; e += 8) {
            int4 c0 = __ldg(reinterpret_cast<const int4*>(gCsr + e));
            int4 c1 = __ldg(reinterpret_cast<const int4*>(gCsr + e + 2));
            int4 c2 = __ldg(reinterpret_cast<const int4*>(gCsr + e + 4));
            int4 c3 = __ldg(reinterpret_cast<const int4*>(gCsr + e + 6));
            float2 f0 = __half22float2(__ldg(x + (size_t)c0.x * 32 + lane));
            float2 f1 = __half22float2(__ldg(x + (size_t)c0.z * 32 + lane));
            float2 f2 = __half22float2(__ldg(x + (size_t)c1.x * 32 + lane));
            float2 f3 = __half22float2(__ldg(x + (size_t)c1.z * 32 + lane));
            float2 f4 = __half22float2(__ldg(x + (size_t)c2.x * 32 + lane));
            float2 f5 = __half22float2(__ldg(x + (size_t)c2.z * 32 + lane));
            float2 f6 = __half22float2(__ldg(x + (size_t)c3.x * 32 + lane));
            float2 f7 = __half22float2(__ldg(x + (size_t)c3.z * 32 + lane));
            ax = fmaf(__int_as_float(c0.y), f0.x, ax); ay = fmaf(__int_as_float(c0.y), f0.y, ay);
            ax = fmaf(__int_as_float(c0.w), f1.x, ax); ay = fmaf(__int_as_float(c0.w), f1.y, ay);
            ax = fmaf(__int_as_float(c1.y), f2.x, ax); ay = fmaf(__int_as_float(c1.y), f2.y, ay);
            ax = fmaf(__int_as_float(c1.w), f3.x, ax); ay = fmaf(__int_as_float(c1.w), f3.y, ay);
            ax = fmaf(__int_as_float(c2.y), f4.x, ax); ay = fmaf(__int_as_float(c2.y), f4.y, ay);
            ax = fmaf(__int_as_float(c2.w), f5.x, ax); ay = fmaf(__int_as_float(c2.w), f5.y, ay);
            ax = fmaf(__int_as_float(c3.y), f6.x, ax); ay = fmaf(__int_as_float(c3.y), f6.y, ay);
            ax = fmaf(__int_as_float(c3.w), f7.x, ax); ay = fmaf(__int_as_float(c3.w), f7.y, ay);
        }
        // pairs
        for (; e + 1 < end; e += 2) {
            int4 c0 = __ldg(reinterpret_cast<const int4*>(gCsr + e));
            float2 f0 = __half22float2(__ldg(x + (size_t)c0.x * 32 + lane));
            float2 f1 = __half22float2(__ldg(x + (size_t)c0.z * 32 + lane));
            ax = fmaf(__int_as_float(c0.y), f0.x, ax); ay = fmaf(__int_as_float(c0.y), f0.y, ay);
            ax = fmaf(__int_as_float(c0.w), f1.x, ax); ay = fmaf(__int_as_float(c0.w), f1.y, ay);
        }
        // tail single
        if (e < end) {
            int2 s0 = __ldg(&gCsr[e]);
            float2 f0 = __half22float2(__ldg(x + (size_t)s0.x * 32 + lane));
            float w0 = __int_as_float(s0.y);
            ax = fmaf(w0, f0.x, ax); ay = fmaf(w0, f0.y, ay);
        }

        float rx = wscale * ax, ry = wscale * ay;
        if (addv) {
            float2 a = __half22float2(__ldg(addv + (size_t)n * 32 + lane));
            rx = fmaf(ascale, a.x, rx);
            ry = fmaf(ascale, a.y, ry);
        }
        if (bias) {
            float2 b = reinterpret_cast<const float2*>(bias)[lane];
            rx = fmaf(bscale, b.x, rx);
            ry = fmaf(bscale, b.y, ry);
        }
        if (HALF_OUT) {
            reinterpret_cast<__half2*>(outv)[(size_t)n * 32 + lane] = __floats2half2_rn(rx, ry);
        } else {
            reinterpret_cast<float2*>(outv)[(size_t)n * 32 + lane] = make_float2(rx, ry);
        }
    }
}

__global__ void fill_tail(float* __restrict__ out, int start, int total)
{
    int i = start + blockIdx.x * blockDim.x + threadIdx.x;
    if (i < total) out[i] = 10.0f;
}

extern "C" void kernel_launch(void* const* d_in, const int* in_sizes, int n_in,
                              void* d_out, int out_size)
{
    const float* features = (const float*)d_in[0];
    const void*  ei       = d_in[1];
    const float* ew       = (const float*)d_in[2];
    const float* W1       = (const float*)d_in[3];
    const float* b1       = (const float*)d_in[4];
    const float* W2       = (const float*)d_in[5];
    const float* b2       = (const float*)d_in[6];
    float*       out      = (float*)d_out;

    const int N = in_sizes[0] / IN_DIM;
    const int E = in_sizes[2];

    __half *X0, *P, *H, *A, *B;
    float  *Wc, *C;
    cudaGetSymbolAddress((void**)&X0, gX0);
    cudaGetSymbolAddress((void**)&P,  gP);
    cudaGetSymbolAddress((void**)&H,  gH);
    cudaGetSymbolAddress((void**)&A,  gA);
    cudaGetSymbolAddress((void**)&B,  gB);
    cudaGetSymbolAddress((void**)&Wc, gWc);
    cudaGetSymbolAddress((void**)&C,  gC);
    int* countPtr;
    cudaGetSymbolAddress((void**)&countPtr, gCount);

    // lazily-created side stream + events (host objects only)
    static cudaStream_t sCsr = nullptr;
    static cudaEvent_t  evFork = nullptr, evCsr = nullptr;
    if (!sCsr) {
        cudaStreamCreateWithFlags(&sCsr, cudaStreamNonBlocking);
        cudaEventCreateWithFlags(&evFork, cudaEventDisableTiming);
        cudaEventCreateWithFlags(&evCsr,  cudaEventDisableTiming);
    }

    // ---- fork: CSR build on side stream ----
    cudaEventRecord(evFork, 0);
    cudaStreamWaitEvent(sCsr, evFork, 0);
    detect_idx_dtype<<<1, 1, 0, sCsr>>>(ei, N);
    cudaMemsetAsync(countPtr, 0, (size_t)N * sizeof(int), sCsr);
    hist_dst<<<((E + 1) / 2 + 255) / 256, 256, 0, sCsr>>>(ei, E);
    scan_rowptr<<<1, 1024, 0, sCsr>>>(N, E);
    warp_partition<<<(NWARPS + 1 + 255) / 256, 256, 0, sCsr>>>(N, E);
    fill_csr<<<((E + 1) / 2 + 255) / 256, 256, 0, sCsr>>>(ei, ew, E);
    cudaEventRecord(evCsr, sCsr);

    // ---- main stream: combined weights + fp32 GEMM (R7-proven) ----
    {
        int tot = IN_DIM * OUT_DIM + OUT_DIM;
        combine_weights<<<(tot + 255) / 256, 256>>>(W1, b1, W2);
    }
    {
        dim3 grid((N + 127) / 128, 1);
        sgemm_h<128, 64, 16, 8, 4><<<grid, 256>>>(N, OUT_DIM, IN_DIM, features, Wc, X0);
    }

    // ---- join ----
    cudaStreamWaitEvent(0, evCsr, 0);

    const float inv = 1.0f / PSCALE;   // 0.25

    // Ps = (prop(X0) + c)/4            [stored scale 4]
    gather64h<true><<<GBLOCKS, GTHREADS>>>((const __half2*)X0, P, nullptr, C,
                                           N, inv, 0.0f, inv);
    // Hs = (prop(4*Ps) + b2)/16        [stored scale 16]
    gather64h<true><<<GBLOCKS, GTHREADS>>>((const __half2*)P, H, nullptr, b2,
                                           N, inv, 0.0f, inv * inv);

    // ---- APPNP: y_{k+1} = (0.9/4)*prop(y_k) + (0.1/4^{k+1})*Hs ----
    const __half* xcur = H;
    float hscale = ALPHA_F;
    for (int k = 0; k < K_STEPS; k++) {
        if (k == K_STEPS - 1) {
            const float wfin = (1.0f - ALPHA_F) * 16.0f * 262144.0f;  // 0.9*16*4^9
            const float afin = ALPHA_F * 16.0f;                        // 1.6
            gather64h<false><<<GBLOCKS, GTHREADS>>>((const __half2*)xcur, out,
                                                    (const __half2*)H, nullptr,
                                                    N, wfin, afin, 0.0f);
        } else {
            hscale *= inv;
            __half* xnext = (k & 1) ? B : A;
            gather64h<true><<<GBLOCKS, GTHREADS>>>((const __half2*)xcur, xnext,
                                                   (const __half2*)H, nullptr,
                                                   N, (1.0f - ALPHA_F) * inv, hscale, 0.0f);
            xcur = xnext;
        }
    }

    // tail (reference returns (x, 10); fill any extra outputs with 10)
    int tail = out_size - N * OUT_DIM;
    if (tail > 0)
        fill_tail<<<(tail + 255) / 256, 256>>>(out, N * OUT_DIM, out_size);
}

// round 11
// speedup vs baseline: 1.1759x; 1.1759x over previous
#include <cuda_runtime.h>
#include <cuda_fp16.h>
#include <cstdint>

// Problem constants (match reference)
#define NMAX      50000
#define EMAX      800000
#define IN_DIM    256
#define H_DIM     128
#define OUT_DIM   64
#define K_STEPS   10
#define ALPHA_F   0.1f

// Scale schedule: every prop divides stored values by 4 (exact, folded into
// fp32 scale constants). x_k true = y_k * (16 * 4^k); H true = Hs * 16.
#define PSCALE    4.0f

// -------- scratch (no allocation allowed -> device globals) --------
__device__ __half gX0[(size_t)NMAX * OUT_DIM];  // X @ (W1@W2)          (scale 1)
__device__ __half gP [(size_t)NMAX * OUT_DIM];  // (prop(X0)+c)/4       (scale 4)
__device__ __half gH [(size_t)NMAX * OUT_DIM];  // (prop(P)+b2)/16      (scale 16)
__device__ __half gA [(size_t)NMAX * OUT_DIM];  // ping  (scale 16*4^k)
__device__ __half gB [(size_t)NMAX * OUT_DIM];  // pong
__device__ __half gWcH[IN_DIM * OUT_DIM];       // fp16(W1 @ W2)  (256x64)
__device__ float  gC [OUT_DIM];                 // b1 @ W2
// CSR scratch
__device__ int    gCount[NMAX];
__device__ int    gRowPtr[NMAX + 1];
__device__ int    gWp[NMAX];
__device__ __align__(16) int2 gCsr[EMAX];       // (src, w-bits) sorted by dst

// ------------- per-block dtype detection (uniform across block) -------------
// int64 data: first 16 int64 values all in [0, N). int32 data: an int64 view
// packs two random indices -> >= 2^32 almost surely (p_fp ~ (2e-5)^16 ~ 0).
__device__ __forceinline__ bool idx_is64(const void* __restrict__ ei, int N)
{
    const long long* p = (const long long*)ei;
    bool ok = true;
#pragma unroll
    for (int i = 0; i < 16; i++) {
        long long v = p[i];
        ok &= (v >= 0 && v < (long long)N);
    }
    return ok;
}

// ------------- CSR build -------------
__global__ void hist_dst(const void* __restrict__ ei, int E, int N)
{
    const bool is64 = idx_is64(ei, N);
    int base = (blockIdx.x * blockDim.x + threadIdx.x) * 4;
    if (base >= E) return;
    if (base + 4 <= E && (E & 3) == 0) {
        int d0, d1, d2, d3;
        if (is64) {
            const long long* p = (const long long*)ei + E + base;
            longlong2 a = *reinterpret_cast<const longlong2*>(p);
            longlong2 b = *reinterpret_cast<const longlong2*>(p + 2);
            d0 = (int)a.x; d1 = (int)a.y; d2 = (int)b.x; d3 = (int)b.y;
        } else {
            int4 v = *reinterpret_cast<const int4*>((const int*)ei + E + base);
            d0 = v.x; d1 = v.y; d2 = v.z; d3 = v.w;
        }
        atomicAdd(&gCount[d0], 1);
        atomicAdd(&gCount[d1], 1);
        atomicAdd(&gCount[d2], 1);
        atomicAdd(&gCount[d3], 1);
    } else {
        for (int e = base; e < min(base + 4, E); e++) {
            int d = is64 ? (int)((const long long*)ei)[E + e] : ((const int*)ei)[E + e];
            atomicAdd(&gCount[d], 1);
        }
    }
}

__global__ void scan_rowptr(int N, int E)
{
    __shared__ int sSum[1024];
    const int tid = threadIdx.x;
    const int chunk = (N + 1023) / 1024;
    const int lo = tid * chunk;
    const int hi = min(lo + chunk, N);

    int s = 0;
    for (int i = lo; i < hi; i++) s += gCount[i];
    sSum[tid] = s;
    __syncthreads();

    for (int off = 1; off < 1024; off <<= 1) {
        int v = (tid >= off) ? sSum[tid - off] : 0;
        __syncthreads();
        sSum[tid] += v;
        __syncthreads();
    }
    int run = (tid == 0) ? 0 : sSum[tid - 1];
    for (int i = lo; i < hi; i++) {
        gRowPtr[i] = run;
        gWp[i]     = run;
        run += gCount[i];
    }
    if (tid == 1023) gRowPtr[N] = E;
}

__global__ void fill_csr(const void* __restrict__ ei, const float* __restrict__ ew,
                         int E, int N)
{
    const bool is64 = idx_is64(ei, N);
    int base = (blockIdx.x * blockDim.x + threadIdx.x) * 4;
    if (base >= E) return;
    if (base + 4 <= E && (E & 3) == 0) {
        int s0, s1, s2, s3, d0, d1, d2, d3;
        if (is64) {
            const long long* ps = (const long long*)ei + base;
            longlong2 a = *reinterpret_cast<const longlong2*>(ps);
            longlong2 b = *reinterpret_cast<const longlong2*>(ps + 2);
            const long long* pd = (const long long*)ei + E + base;
            longlong2 c = *reinterpret_cast<const longlong2*>(pd);
            longlong2 d = *reinterpret_cast<const longlong2*>(pd + 2);
            s0 = (int)a.x; s1 = (int)a.y; s2 = (int)b.x; s3 = (int)b.y;
            d0 = (int)c.x; d1 = (int)c.y; d2 = (int)d.x; d3 = (int)d.y;
        } else {
            int4 sv = *reinterpret_cast<const int4*>((const int*)ei + base);
            int4 dv = *reinterpret_cast<const int4*>((const int*)ei + E + base);
            s0 = sv.x; s1 = sv.y; s2 = sv.z; s3 = sv.w;
            d0 = dv.x; d1 = dv.y; d2 = dv.z; d3 = dv.w;
        }
        float4 wv = *reinterpret_cast<const float4*>(ew + base);
        int p0 = atomicAdd(&gWp[d0], 1); gCsr[p0] = make_int2(s0, __float_as_int(wv.x));
        int p1 = atomicAdd(&gWp[d1], 1); gCsr[p1] = make_int2(s1, __float_as_int(wv.y));
        int p2 = atomicAdd(&gWp[d2], 1); gCsr[p2] = make_int2(s2, __float_as_int(wv.z));
        int p3 = atomicAdd(&gWp[d3], 1); gCsr[p3] = make_int2(s3, __float_as_int(wv.w));
    } else {
        for (int e = base; e < min(base + 4, E); e++) {
            int s, d;
            if (is64) {
                s = (int)((const long long*)ei)[e];
                d = (int)((const long long*)ei)[E + e];
            } else {
                s = ((const int*)ei)[e];
                d = ((const int*)ei)[E + e];
            }
            int pos = atomicAdd(&gWp[d], 1);
            gCsr[pos] = make_int2(s, __float_as_int(ew[e]));
        }
    }
}

// ------------- tiny: WcH = fp16(W1 @ W2) (256x64), c = b1 @ W2 (64) -------------
__global__ void combine_weights(const float* __restrict__ W1,
                                const float* __restrict__ b1,
                                const float* __restrict__ W2)
{
    int idx = blockIdx.x * blockDim.x + threadIdx.x;
    if (idx < IN_DIM * OUT_DIM) {
        int i = idx >> 6, j = idx & 63;
        float s = 0.0f;
        const float* w1r = W1 + (size_t)i * H_DIM;
#pragma unroll 8
        for (int k = 0; k < H_DIM; k++)
            s += w1r[k] * W2[(size_t)k * OUT_DIM + j];
        gWcH[idx] = __float2half_rn(s);
    } else if (idx < IN_DIM * OUT_DIM + OUT_DIM) {
        int j = idx - IN_DIM * OUT_DIM;
        float s = 0.0f;
#pragma unroll 8
        for (int k = 0; k < H_DIM; k++)
            s += b1[k] * W2[(size_t)k * OUT_DIM + j];
        gC[j] = s;
    }
}

// ------------- tensor-core GEMM: X0[M,64] = fp16(A[M,256]) @ WcH[256,64] -------------
// 256 threads = 8 warps; 128-row tile; K streamed in 64-chunks.
// Fragment layout / mma / store indexing identical to the numerically-verified R9 kernel.
__global__ void __launch_bounds__(256) gemm_mma(int M,
                                                const float* __restrict__ A,
                                                const __half* __restrict__ Bh,
                                                __half* __restrict__ Ch)
{
    __shared__ __half As[128][72];   // pad 72: conflict-free ldmatrix
    __shared__ __half Bs[64][72];

    const int tid  = threadIdx.x;
    const int wid  = tid >> 5;
    const int lane = tid & 31;
    const int rowBase = blockIdx.x * 128;

    float acc[8][4];
#pragma unroll
    for (int n = 0; n < 8; n++)
#pragma unroll
        for (int j = 0; j < 4; j++) acc[n][j] = 0.0f;

    for (int c = 0; c < IN_DIM / 64; c++) {
        __syncthreads();
        // A chunk: 128 rows x 64 cols fp32 -> fp16 (2048 float4)
#pragma unroll
        for (int i = 0; i < 8; i++) {
            int idx = tid + i * 256;
            int r = idx >> 4, cv = idx & 15;
            int grow = rowBase + r;
            float4 v = make_float4(0.f, 0.f, 0.f, 0.f);
            if (grow < M)
                v = *reinterpret_cast<const float4*>(A + (size_t)grow * IN_DIM + c * 64 + cv * 4);
            __half2* dst = reinterpret_cast<__half2*>(&As[r][cv * 4]);
            dst[0] = __floats2half2_rn(v.x, v.y);
            dst[1] = __floats2half2_rn(v.z, v.w);
        }
        // B chunk: 64x64 fp16 raw copy (512 uint4)
#pragma unroll
        for (int i = 0; i < 2; i++) {
            int idx = tid + i * 256;
            int r = idx >> 3, cv = idx & 7;
            uint4 v = *reinterpret_cast<const uint4*>(Bh + (size_t)(c * 64 + r) * 64 + cv * 8);
            *reinterpret_cast<uint4*>(&Bs[r][cv * 8]) = v;
        }
        __syncthreads();

#pragma unroll
        for (int k0 = 0; k0 < 64; k0 += 16) {
            uint32_t a0, a1, a2, a3;
            {
                uint32_t sa = (uint32_t)__cvta_generic_to_shared(
                    &As[16 * wid + (lane & 15)][k0 + 8 * (lane >> 4)]);
                asm volatile("ldmatrix.sync.aligned.m8n8.x4.shared.b16 {%0,%1,%2,%3}, [%4];"
                             : "=r"(a0), "=r"(a1), "=r"(a2), "=r"(a3) : "r"(sa));
            }
#pragma unroll
            for (int n = 0; n < 8; n++) {
                uint32_t b0, b1;
                uint32_t sb = (uint32_t)__cvta_generic_to_shared(
                    &Bs[k0 + (lane & 15)][n * 8]);
                asm volatile("ldmatrix.sync.aligned.m8n8.x2.trans.shared.b16 {%0,%1}, [%2];"
                             : "=r"(b0), "=r"(b1) : "r"(sb));
                asm volatile("mma.sync.aligned.m16n8k16.row.col.f32.f16.f16.f32 "
                             "{%0,%1,%2,%3}, {%4,%5,%6,%7}, {%8,%9}, {%0,%1,%2,%3};"
                             : "+f"(acc[n][0]), "+f"(acc[n][1]), "+f"(acc[n][2]), "+f"(acc[n][3])
                             : "r"(a0), "r"(a1), "r"(a2), "r"(a3), "r"(b0), "r"(b1));
            }
        }
    }

    int row  = lane >> 2;
    int colp = (lane & 3) * 2;
#pragma unroll
    for (int n = 0; n < 8; n++) {
        int g0 = rowBase + 16 * wid + row;
        if (g0 < M)
            *reinterpret_cast<__half2*>(Ch + (size_t)g0 * 64 + n * 8 + colp) =
                __floats2half2_rn(acc[n][0], acc[n][1]);
        int g1 = g0 + 8;
        if (g1 < M)
            *reinterpret_cast<__half2*>(Ch + (size_t)g1 * 64 + n * 8 + colp) =
                __floats2half2_rn(acc[n][2], acc[n][3]);
    }
}

// ------------- CSR gather prop (R7-proven exact form) -------------
// out[n,:] = wscale*sum_e w_e*x[src_e,:] + ascale*addv[n,:] + bscale*bias[:]
// One warp per node; lane l owns half2 pair {2l, 2l+1}. fp32 accumulation.
template<bool HALF_OUT>
__global__ void gather64h(const __half2* __restrict__ x,
                          void* __restrict__ outv,
                          const __half2* __restrict__ addv,  // may be null
                          const float* __restrict__ bias,    // fp32[64], may be null
                          int N, float wscale, float ascale, float bscale)
{
    int warp = (blockIdx.x * blockDim.x + threadIdx.x) >> 5;
    int lane = threadIdx.x & 31;
    if (warp >= N) return;

    int e   = gRowPtr[warp];
    int end = gRowPtr[warp + 1];

    float ax = 0.f, ay = 0.f;

    for (; e + 3 < end; e += 4) {
        int2 s0 = __ldg(&gCsr[e]);
        int2 s1 = __ldg(&gCsr[e + 1]);
        int2 s2 = __ldg(&gCsr[e + 2]);
        int2 s3 = __ldg(&gCsr[e + 3]);
        float2 f0 = __half22float2(__ldg(x + (size_t)s0.x * 32 + lane));
        float2 f1 = __half22float2(__ldg(x + (size_t)s1.x * 32 + lane));
        float2 f2 = __half22float2(__ldg(x + (size_t)s2.x * 32 + lane));
        float2 f3 = __half22float2(__ldg(x + (size_t)s3.x * 32 + lane));
        float w0 = __int_as_float(s0.y);
        float w1 = __int_as_float(s1.y);
        float w2 = __int_as_float(s2.y);
        float w3 = __int_as_float(s3.y);
        ax = fmaf(w0, f0.x, ax); ay = fmaf(w0, f0.y, ay);
        ax = fmaf(w1, f1.x, ax); ay = fmaf(w1, f1.y, ay);
        ax = fmaf(w2, f2.x, ax); ay = fmaf(w2, f2.y, ay);
        ax = fmaf(w3, f3.x, ax); ay = fmaf(w3, f3.y, ay);
    }
    for (; e < end; e++) {
        int2 s0 = __ldg(&gCsr[e]);
        float2 f0 = __half22float2(__ldg(x + (size_t)s0.x * 32 + lane));
        float w0 = __int_as_float(s0.y);
        ax = fmaf(w0, f0.x, ax); ay = fmaf(w0, f0.y, ay);
    }

    float rx = wscale * ax, ry = wscale * ay;
    if (addv) {
        float2 a = __half22float2(__ldg(addv + (size_t)warp * 32 + lane));
        rx = fmaf(ascale, a.x, rx);
        ry = fmaf(ascale, a.y, ry);
    }
    if (bias) {
        float2 b = reinterpret_cast<const float2*>(bias)[lane];
        rx = fmaf(bscale, b.x, rx);
        ry = fmaf(bscale, b.y, ry);
    }
    if (HALF_OUT) {
        reinterpret_cast<__half2*>(outv)[(size_t)warp * 32 + lane] = __floats2half2_rn(rx, ry);
    } else {
        reinterpret_cast<float2*>(outv)[(size_t)warp * 32 + lane] = make_float2(rx, ry);
    }
}

__global__ void fill_tail(float* __restrict__ out, int start, int total)
{
    int i = start + blockIdx.x * blockDim.x + threadIdx.x;
    if (i < total) out[i] = 10.0f;
}

extern "C" void kernel_launch(void* const* d_in, const int* in_sizes, int n_in,
                              void* d_out, int out_size)
{
    const float* features = (const float*)d_in[0];
    const void*  ei       = d_in[1];
    const float* ew       = (const float*)d_in[2];
    const float* W1       = (const float*)d_in[3];
    const float* b1       = (const float*)d_in[4];
    const float* W2       = (const float*)d_in[5];
    const float* b2       = (const float*)d_in[6];
    float*       out      = (float*)d_out;

    const int N = in_sizes[0] / IN_DIM;
    const int E = in_sizes[2];

    __half *X0, *P, *H, *A, *B, *WcH;
    float  *C;
    cudaGetSymbolAddress((void**)&X0,  gX0);
    cudaGetSymbolAddress((void**)&P,   gP);
    cudaGetSymbolAddress((void**)&H,   gH);
    cudaGetSymbolAddress((void**)&A,   gA);
    cudaGetSymbolAddress((void**)&B,   gB);
    cudaGetSymbolAddress((void**)&WcH, gWcH);
    cudaGetSymbolAddress((void**)&C,   gC);
    int* countPtr;
    cudaGetSymbolAddress((void**)&countPtr, gCount);

    // lazily-created side stream + events (host objects only)
    static cudaStream_t sCsr = nullptr;
    static cudaEvent_t  evFork = nullptr, evCsr = nullptr;
    if (!sCsr) {
        cudaStreamCreateWithFlags(&sCsr, cudaStreamNonBlocking);
        cudaEventCreateWithFlags(&evFork, cudaEventDisableTiming);
        cudaEventCreateWithFlags(&evCsr,  cudaEventDisableTiming);
    }

    // ---- fork: CSR build on side stream ----
    cudaEventRecord(evFork, 0);
    cudaStreamWaitEvent(sCsr, evFork, 0);
    cudaMemsetAsync(countPtr, 0, (size_t)N * sizeof(int), sCsr);
    hist_dst<<<((E + 3) / 4 + 255) / 256, 256, 0, sCsr>>>(ei, E, N);
    scan_rowptr<<<1, 1024, 0, sCsr>>>(N, E);
    fill_csr<<<((E + 3) / 4 + 255) / 256, 256, 0, sCsr>>>(ei, ew, E, N);
    cudaEventRecord(evCsr, sCsr);

    // ---- main stream: combined weights + tensor-core GEMM ----
    {
        int tot = IN_DIM * OUT_DIM + OUT_DIM;
        combine_weights<<<(tot + 255) / 256, 256>>>(W1, b1, W2);
    }
    gemm_mma<<<(N + 127) / 128, 256>>>(N, features, WcH, X0);

    // ---- join ----
    cudaStreamWaitEvent(0, evCsr, 0);

    const int gthreads = 256;
    const int wpb = gthreads / 32;
    const int gblocks = (N + wpb - 1) / wpb;
    const float inv = 1.0f / PSCALE;   // 0.25

    // Ps = (prop(X0) + c)/4            [stored scale 4]
    gather64h<true><<<gblocks, gthreads>>>((const __half2*)X0, P, nullptr, C,
                                           N, inv, 0.0f, inv);
    // Hs = (prop(4*Ps) + b2)/16        [stored scale 16]
    gather64h<true><<<gblocks, gthreads>>>((const __half2*)P, H, nullptr, b2,
                                           N, inv, 0.0f, inv * inv);

    // ---- APPNP: y_{k+1} = (0.9/4)*prop(y_k) + (0.1/4^{k+1})*Hs ----
    const __half* xcur = H;
    float hscale = ALPHA_F;
    for (int k = 0; k < K_STEPS; k++) {
        if (k == K_STEPS - 1) {
            const float wfin = (1.0f - ALPHA_F) * 16.0f * 262144.0f;  // 0.9*16*4^9
            const float afin = ALPHA_F * 16.0f;                        // 1.6
            gather64h<false><<<gblocks, gthreads>>>((const __half2*)xcur, out,
                                                    (const __half2*)H, nullptr,
                                                    N, wfin, afin, 0.0f);
        } else {
            hscale *= inv;
            __half* xnext = (k & 1) ? B : A;
            gather64h<true><<<gblocks, gthreads>>>((const __half2*)xcur, xnext,
                                                   (const __half2*)H, nullptr,
                                                   N, (1.0f - ALPHA_F) * inv, hscale, 0.0f);
            xcur = xnext;
        }
    }

    // tail (reference returns (x, 10); fill any extra outputs with 10)
    int tail = out_size - N * OUT_DIM;
    if (tail > 0)
        fill_tail<<<(tail + 255) / 256, 256>>>(out, N * OUT_DIM, out_size);
}

// round 12
// speedup vs baseline: 1.2143x; 1.0326x over previous
#include <cuda_runtime.h>
#include <cuda_fp16.h>
#include <cstdint>

// Problem constants (match reference)
#define NMAX      50000
#define IN_DIM    256
#define H_DIM     128
#define OUT_DIM   64
#define K_STEPS   10
#define ALPHA_F   0.1f

// Scale schedule: every prop divides stored values by 4 (exact, folded into
// fp32 scale constants). x_k true = y_k * (16 * 4^k); H true = Hs * 16.
#define PSCALE    4.0f

// fixed-slot bucket layout: SLOTS edge slots per node (max degree << SLOTS)
#define SLOTS     128

// -------- scratch (no allocation allowed -> device globals) --------
__device__ __half gX0[(size_t)NMAX * OUT_DIM];  // X @ (W1@W2)          (scale 1)
__device__ __half gP [(size_t)NMAX * OUT_DIM];  // (prop(X0)+c)/4       (scale 4)
__device__ __half gH [(size_t)NMAX * OUT_DIM];  // (prop(P)+b2)/16      (scale 16)
__device__ __half gA [(size_t)NMAX * OUT_DIM];  // ping  (scale 16*4^k)
__device__ __half gB [(size_t)NMAX * OUT_DIM];  // pong
__device__ __half gWcH[IN_DIM * OUT_DIM];       // fp16(W1 @ W2)  (256x64)
__device__ float  gC [OUT_DIM];                 // b1 @ W2
// bucket scratch
__device__ int    gCount[NMAX];                 // per-node edge count (atomic wp)
__device__ __align__(16) int2 gSlot[(size_t)NMAX * SLOTS];  // (src, w-bits)

// ------------- per-block dtype detection (uniform across block) -------------
// int64 data: first 16 int64 values all in [0, N). int32 data: an int64 view
// packs two random indices -> >= 2^32 almost surely.
__device__ __forceinline__ bool idx_is64(const void* __restrict__ ei, int N)
{
    const long long* p = (const long long*)ei;
    bool ok = true;
#pragma unroll
    for (int i = 0; i < 16; i++) {
        long long v = p[i];
        ok &= (v >= 0 && v < (long long)N);
    }
    return ok;
}

// ------------- single-pass bucket fill (no hist, no scan) -------------
__global__ void fill_slots(const void* __restrict__ ei, const float* __restrict__ ew,
                           int E, int N)
{
    const bool is64 = idx_is64(ei, N);
    int base = (blockIdx.x * blockDim.x + threadIdx.x) * 4;
    if (base >= E) return;
    if (base + 4 <= E && (E & 3) == 0) {
        int s0, s1, s2, s3, d0, d1, d2, d3;
        if (is64) {
            const long long* ps = (const long long*)ei + base;
            longlong2 a = *reinterpret_cast<const longlong2*>(ps);
            longlong2 b = *reinterpret_cast<const longlong2*>(ps + 2);
            const long long* pd = (const long long*)ei + E + base;
            longlong2 c = *reinterpret_cast<const longlong2*>(pd);
            longlong2 d = *reinterpret_cast<const longlong2*>(pd + 2);
            s0 = (int)a.x; s1 = (int)a.y; s2 = (int)b.x; s3 = (int)b.y;
            d0 = (int)c.x; d1 = (int)c.y; d2 = (int)d.x; d3 = (int)d.y;
        } else {
            int4 sv = *reinterpret_cast<const int4*>((const int*)ei + base);
            int4 dv = *reinterpret_cast<const int4*>((const int*)ei + E + base);
            s0 = sv.x; s1 = sv.y; s2 = sv.z; s3 = sv.w;
            d0 = dv.x; d1 = dv.y; d2 = dv.z; d3 = dv.w;
        }
        float4 wv = *reinterpret_cast<const float4*>(ew + base);
        int p0 = atomicAdd(&gCount[d0], 1);
        gSlot[(size_t)d0 * SLOTS + p0] = make_int2(s0, __float_as_int(wv.x));
        int p1 = atomicAdd(&gCount[d1], 1);
        gSlot[(size_t)d1 * SLOTS + p1] = make_int2(s1, __float_as_int(wv.y));
        int p2 = atomicAdd(&gCount[d2], 1);
        gSlot[(size_t)d2 * SLOTS + p2] = make_int2(s2, __float_as_int(wv.z));
        int p3 = atomicAdd(&gCount[d3], 1);
        gSlot[(size_t)d3 * SLOTS + p3] = make_int2(s3, __float_as_int(wv.w));
    } else {
        for (int e = base; e < min(base + 4, E); e++) {
            int s, d;
            if (is64) {
                s = (int)((const long long*)ei)[e];
                d = (int)((const long long*)ei)[E + e];
            } else {
                s = ((const int*)ei)[e];
                d = ((const int*)ei)[E + e];
            }
            int pos = atomicAdd(&gCount[d], 1);
            gSlot[(size_t)d * SLOTS + pos] = make_int2(s, __float_as_int(ew[e]));
        }
    }
}

// ------------- tiny: WcH = fp16(W1 @ W2) (256x64), c = b1 @ W2 (64) -------------
__global__ void combine_weights(const float* __restrict__ W1,
                                const float* __restrict__ b1,
                                const float* __restrict__ W2)
{
    int idx = blockIdx.x * blockDim.x + threadIdx.x;
    if (idx < IN_DIM * OUT_DIM) {
        int i = idx >> 6, j = idx & 63;
        float s = 0.0f;
        const float* w1r = W1 + (size_t)i * H_DIM;
#pragma unroll 8
        for (int k = 0; k < H_DIM; k++)
            s += w1r[k] * W2[(size_t)k * OUT_DIM + j];
        gWcH[idx] = __float2half_rn(s);
    } else if (idx < IN_DIM * OUT_DIM + OUT_DIM) {
        int j = idx - IN_DIM * OUT_DIM;
        float s = 0.0f;
#pragma unroll 8
        for (int k = 0; k < H_DIM; k++)
            s += b1[k] * W2[(size_t)k * OUT_DIM + j];
        gC[j] = s;
    }
}

// ------------- tensor-core GEMM: X0[M,64] = fp16(A[M,256]) @ WcH[256,64] -------------
// (verbatim from R11 — numerically verified)
__global__ void __launch_bounds__(256) gemm_mma(int M,
                                                const float* __restrict__ A,
                                                const __half* __restrict__ Bh,
                                                __half* __restrict__ Ch)
{
    __shared__ __half As[128][72];
    __shared__ __half Bs[64][72];

    const int tid  = threadIdx.x;
    const int wid  = tid >> 5;
    const int lane = tid & 31;
    const int rowBase = blockIdx.x * 128;

    float acc[8][4];
#pragma unroll
    for (int n = 0; n < 8; n++)
#pragma unroll
        for (int j = 0; j < 4; j++) acc[n][j] = 0.0f;

    for (int c = 0; c < IN_DIM / 64; c++) {
        __syncthreads();
#pragma unroll
        for (int i = 0; i < 8; i++) {
            int idx = tid + i * 256;
            int r = idx >> 4, cv = idx & 15;
            int grow = rowBase + r;
            float4 v = make_float4(0.f, 0.f, 0.f, 0.f);
            if (grow < M)
                v = *reinterpret_cast<const float4*>(A + (size_t)grow * IN_DIM + c * 64 + cv * 4);
            __half2* dst = reinterpret_cast<__half2*>(&As[r][cv * 4]);
            dst[0] = __floats2half2_rn(v.x, v.y);
            dst[1] = __floats2half2_rn(v.z, v.w);
        }
#pragma unroll
        for (int i = 0; i < 2; i++) {
            int idx = tid + i * 256;
            int r = idx >> 3, cv = idx & 7;
            uint4 v = *reinterpret_cast<const uint4*>(Bh + (size_t)(c * 64 + r) * 64 + cv * 8);
            *reinterpret_cast<uint4*>(&Bs[r][cv * 8]) = v;
        }
        __syncthreads();

#pragma unroll
        for (int k0 = 0; k0 < 64; k0 += 16) {
            uint32_t a0, a1, a2, a3;
            {
                uint32_t sa = (uint32_t)__cvta_generic_to_shared(
                    &As[16 * wid + (lane & 15)][k0 + 8 * (lane >> 4)]);
                asm volatile("ldmatrix.sync.aligned.m8n8.x4.shared.b16 {%0,%1,%2,%3}, [%4];"
                             : "=r"(a0), "=r"(a1), "=r"(a2), "=r"(a3) : "r"(sa));
            }
#pragma unroll
            for (int n = 0; n < 8; n++) {
                uint32_t b0, b1;
                uint32_t sb = (uint32_t)__cvta_generic_to_shared(
                    &Bs[k0 + (lane & 15)][n * 8]);
                asm volatile("ldmatrix.sync.aligned.m8n8.x2.trans.shared.b16 {%0,%1}, [%2];"
                             : "=r"(b0), "=r"(b1) : "r"(sb));
                asm volatile("mma.sync.aligned.m16n8k16.row.col.f32.f16.f16.f32 "
                             "{%0,%1,%2,%3}, {%4,%5,%6,%7}, {%8,%9}, {%0,%1,%2,%3};"
                             : "+f"(acc[n][0]), "+f"(acc[n][1]), "+f"(acc[n][2]), "+f"(acc[n][3])
                             : "r"(a0), "r"(a1), "r"(a2), "r"(a3), "r"(b0), "r"(b1));
            }
        }
    }

    int row  = lane >> 2;
    int colp = (lane & 3) * 2;
#pragma unroll
    for (int n = 0; n < 8; n++) {
        int g0 = rowBase + 16 * wid + row;
        if (g0 < M)
            *reinterpret_cast<__half2*>(Ch + (size_t)g0 * 64 + n * 8 + colp) =
                __floats2half2_rn(acc[n][0], acc[n][1]);
        int g1 = g0 + 8;
        if (g1 < M)
            *reinterpret_cast<__half2*>(Ch + (size_t)g1 * 64 + n * 8 + colp) =
                __floats2half2_rn(acc[n][2], acc[n][3]);
    }
}

// ------------- bucket gather prop (R7-proven inner loop) -------------
// out[n,:] = wscale*sum_e w_e*x[src_e,:] + ascale*addv[n,:] + bscale*bias[:]
// One warp per node; lane l owns half2 pair {2l, 2l+1}. fp32 accumulation.
template<bool HALF_OUT>
__global__ void gather64h(const __half2* __restrict__ x,
                          void* __restrict__ outv,
                          const __half2* __restrict__ addv,  // may be null
                          const float* __restrict__ bias,    // fp32[64], may be null
                          int N, float wscale, float ascale, float bscale)
{
    int warp = (blockIdx.x * blockDim.x + threadIdx.x) >> 5;
    int lane = threadIdx.x & 31;
    if (warp >= N) return;

    const int2* __restrict__ sl = gSlot + (size_t)warp * SLOTS;
    int e   = 0;
    int end = gCount[warp];

    float ax = 0.f, ay = 0.f;

    for (; e + 3 < end; e += 4) {
        int2 s0 = __ldg(&sl[e]);
        int2 s1 = __ldg(&sl[e + 1]);
        int2 s2 = __ldg(&sl[e + 2]);
        int2 s3 = __ldg(&sl[e + 3]);
        float2 f0 = __half22float2(__ldg(x + (size_t)s0.x * 32 + lane));
        float2 f1 = __half22float2(__ldg(x + (size_t)s1.x * 32 + lane));
        float2 f2 = __half22float2(__ldg(x + (size_t)s2.x * 32 + lane));
        float2 f3 = __half22float2(__ldg(x + (size_t)s3.x * 32 + lane));
        float w0 = __int_as_float(s0.y);
        float w1 = __int_as_float(s1.y);
        float w2 = __int_as_float(s2.y);
        float w3 = __int_as_float(s3.y);
        ax = fmaf(w0, f0.x, ax); ay = fmaf(w0, f0.y, ay);
        ax = fmaf(w1, f1.x, ax); ay = fmaf(w1, f1.y, ay);
        ax = fmaf(w2, f2.x, ax); ay = fmaf(w2, f2.y, ay);
        ax = fmaf(w3, f3.x, ax); ay = fmaf(w3, f3.y, ay);
    }
    for (; e < end; e++) {
        int2 s0 = __ldg(&sl[e]);
        float2 f0 = __half22float2(__ldg(x + (size_t)s0.x * 32 + lane));
        float w0 = __int_as_float(s0.y);
        ax = fmaf(w0, f0.x, ax); ay = fmaf(w0, f0.y, ay);
    }

    float rx = wscale * ax, ry = wscale * ay;
    if (addv) {
        float2 a = __half22float2(__ldg(addv + (size_t)warp * 32 + lane));
        rx = fmaf(ascale, a.x, rx);
        ry = fmaf(ascale, a.y, ry);
    }
    if (bias) {
        float2 b = reinterpret_cast<const float2*>(bias)[lane];
        rx = fmaf(bscale, b.x, rx);
        ry = fmaf(bscale, b.y, ry);
    }
    if (HALF_OUT) {
        reinterpret_cast<__half2*>(outv)[(size_t)warp * 32 + lane] = __floats2half2_rn(rx, ry);
    } else {
        reinterpret_cast<float2*>(outv)[(size_t)warp * 32 + lane] = make_float2(rx, ry);
    }
}

__global__ void fill_tail(float* __restrict__ out, int start, int total)
{
    int i = start + blockIdx.x * blockDim.x + threadIdx.x;
    if (i < total) out[i] = 10.0f;
}

extern "C" void kernel_launch(void* const* d_in, const int* in_sizes, int n_in,
                              void* d_out, int out_size)
{
    const float* features = (const float*)d_in[0];
    const void*  ei       = d_in[1];
    const float* ew       = (const float*)d_in[2];
    const float* W1       = (const float*)d_in[3];
    const float* b1       = (const float*)d_in[4];
    const float* W2       = (const float*)d_in[5];
    const float* b2       = (const float*)d_in[6];
    float*       out      = (float*)d_out;

    const int N = in_sizes[0] / IN_DIM;
    const int E = in_sizes[2];

    __half *X0, *P, *H, *A, *B, *WcH;
    float  *C;
    cudaGetSymbolAddress((void**)&X0,  gX0);
    cudaGetSymbolAddress((void**)&P,   gP);
    cudaGetSymbolAddress((void**)&H,   gH);
    cudaGetSymbolAddress((void**)&A,   gA);
    cudaGetSymbolAddress((void**)&B,   gB);
    cudaGetSymbolAddress((void**)&WcH, gWcH);
    cudaGetSymbolAddress((void**)&C,   gC);
    int* countPtr;
    cudaGetSymbolAddress((void**)&countPtr, gCount);

    // lazily-created side stream + events (host objects only)
    static cudaStream_t sCsr = nullptr;
    static cudaEvent_t  evFork = nullptr, evCsr = nullptr;
    if (!sCsr) {
        cudaStreamCreateWithFlags(&sCsr, cudaStreamNonBlocking);
        cudaEventCreateWithFlags(&evFork, cudaEventDisableTiming);
        cudaEventCreateWithFlags(&evCsr,  cudaEventDisableTiming);
    }

    // ---- fork: bucket build on side stream (single pass; no hist, no scan) ----
    cudaEventRecord(evFork, 0);
    cudaStreamWaitEvent(sCsr, evFork, 0);
    cudaMemsetAsync(countPtr, 0, (size_t)N * sizeof(int), sCsr);
    fill_slots<<<((E + 3) / 4 + 255) / 256, 256, 0, sCsr>>>(ei, ew, E, N);
    cudaEventRecord(evCsr, sCsr);

    // ---- main stream: combined weights + tensor-core GEMM ----
    {
        int tot = IN_DIM * OUT_DIM + OUT_DIM;
        combine_weights<<<(tot + 255) / 256, 256>>>(W1, b1, W2);
    }
    gemm_mma<<<(N + 127) / 128, 256>>>(N, features, WcH, X0);

    // ---- join ----
    cudaStreamWaitEvent(0, evCsr, 0);

    const int gthreads = 256;
    const int wpb = gthreads / 32;
    const int gblocks = (N + wpb - 1) / wpb;
    const float inv = 1.0f / PSCALE;   // 0.25

    // Ps = (prop(X0) + c)/4            [stored scale 4]
    gather64h<true><<<gblocks, gthreads>>>((const __half2*)X0, P, nullptr, C,
                                           N, inv, 0.0f, inv);
    // Hs = (prop(4*Ps) + b2)/16        [stored scale 16]
    gather64h<true><<<gblocks, gthreads>>>((const __half2*)P, H, nullptr, b2,
                                           N, inv, 0.0f, inv * inv);

    // ---- APPNP: y_{k+1} = (0.9/4)*prop(y_k) + (0.1/4^{k+1})*Hs ----
    const __half* xcur = H;
    float hscale = ALPHA_F;
    for (int k = 0; k < K_STEPS; k++) {
        if (k == K_STEPS - 1) {
            const float wfin = (1.0f - ALPHA_F) * 16.0f * 262144.0f;  // 0.9*16*4^9
            const float afin = ALPHA_F * 16.0f;                        // 1.6
            gather64h<false><<<gblocks, gthreads>>>((const __half2*)xcur, out,
                                                    (const __half2*)H, nullptr,
                                                    N, wfin, afin, 0.0f);
        } else {
            hscale *= inv;
            __half* xnext = (k & 1) ? B : A;
            gather64h<true><<<gblocks, gthreads>>>((const __half2*)xcur, xnext,
                                                   (const __half2*)H, nullptr,
                                                   N, (1.0f - ALPHA_F) * inv, hscale, 0.0f);
            xcur = xnext;
        }
    }

    // tail (reference returns (x, 10); fill any extra outputs with 10)
    int tail = out_size - N * OUT_DIM;
    if (tail > 0)
        fill_tail<<<(tail + 255) / 256, 256>>>(out, N * OUT_DIM, out_size);
}

// round 13
// speedup vs baseline: 1.4287x; 1.1766x over previous
#include <cuda_runtime.h>
#include <cuda_fp16.h>
#include <cstdint>

// Problem constants (match reference)
#define NMAX      50000
#define IN_DIM    256
#define H_DIM     128
#define OUT_DIM   64
#define K_STEPS   10
#define ALPHA_F   0.1f

// Scale schedule: every prop divides stored values by 4 (exact, folded into
// fp32 scale constants). x_k true = y_k * (16 * 4^k); H true = Hs * 16.
#define PSCALE    4.0f

// fixed-slot bucket layout: SLOTS edge slots per node (max degree << SLOTS)
#define SLOTS     128

// -------- scratch (no allocation allowed -> device globals) --------
__device__ __half gX0[(size_t)NMAX * OUT_DIM];  // X @ (W1@W2)          (scale 1)
__device__ __half gP [(size_t)NMAX * OUT_DIM];  // (prop(X0)+c)/4       (scale 4)
__device__ __half gH [(size_t)NMAX * OUT_DIM];  // (prop(P)+b2)/16      (scale 16)
__device__ __half gA [(size_t)NMAX * OUT_DIM];  // ping  (scale 16*4^k)
__device__ __half gB [(size_t)NMAX * OUT_DIM];  // pong
__device__ __half gWcH[IN_DIM * OUT_DIM];       // fp16(W1 @ W2)  (256x64)
__device__ float  gC [OUT_DIM];                 // b1 @ W2
// bucket scratch
__device__ int    gCount[NMAX];                 // per-node edge count (atomic wp)
__device__ __align__(16) int2 gSlot[(size_t)NMAX * SLOTS];  // (src, w-bits)

// ------------- per-block dtype detection (uniform across block) -------------
__device__ __forceinline__ bool idx_is64(const void* __restrict__ ei, int N)
{
    const long long* p = (const long long*)ei;
    bool ok = true;
#pragma unroll
    for (int i = 0; i < 16; i++) {
        long long v = p[i];
        ok &= (v >= 0 && v < (long long)N);
    }
    return ok;
}

// ------------- single-pass bucket fill (no hist, no scan) -------------
__global__ void fill_slots(const void* __restrict__ ei, const float* __restrict__ ew,
                           int E, int N)
{
    const bool is64 = idx_is64(ei, N);
    int base = (blockIdx.x * blockDim.x + threadIdx.x) * 4;
    if (base >= E) return;
    if (base + 4 <= E && (E & 3) == 0) {
        int s0, s1, s2, s3, d0, d1, d2, d3;
        if (is64) {
            const long long* ps = (const long long*)ei + base;
            longlong2 a = *reinterpret_cast<const longlong2*>(ps);
            longlong2 b = *reinterpret_cast<const longlong2*>(ps + 2);
            const long long* pd = (const long long*)ei + E + base;
            longlong2 c = *reinterpret_cast<const longlong2*>(pd);
            longlong2 d = *reinterpret_cast<const longlong2*>(pd + 2);
            s0 = (int)a.x; s1 = (int)a.y; s2 = (int)b.x; s3 = (int)b.y;
            d0 = (int)c.x; d1 = (int)c.y; d2 = (int)d.x; d3 = (int)d.y;
        } else {
            int4 sv = *reinterpret_cast<const int4*>((const int*)ei + base);
            int4 dv = *reinterpret_cast<const int4*>((const int*)ei + E + base);
            s0 = sv.x; s1 = sv.y; s2 = sv.z; s3 = sv.w;
            d0 = dv.x; d1 = dv.y; d2 = dv.z; d3 = dv.w;
        }
        float4 wv = *reinterpret_cast<const float4*>(ew + base);
        int p0 = atomicAdd(&gCount[d0], 1);
        gSlot[(size_t)d0 * SLOTS + p0] = make_int2(s0, __float_as_int(wv.x));
        int p1 = atomicAdd(&gCount[d1], 1);
        gSlot[(size_t)d1 * SLOTS + p1] = make_int2(s1, __float_as_int(wv.y));
        int p2 = atomicAdd(&gCount[d2], 1);
        gSlot[(size_t)d2 * SLOTS + p2] = make_int2(s2, __float_as_int(wv.z));
        int p3 = atomicAdd(&gCount[d3], 1);
        gSlot[(size_t)d3 * SLOTS + p3] = make_int2(s3, __float_as_int(wv.w));
    } else {
        for (int e = base; e < min(base + 4, E); e++) {
            int s, d;
            if (is64) {
                s = (int)((const long long*)ei)[e];
                d = (int)((const long long*)ei)[E + e];
            } else {
                s = ((const int*)ei)[e];
                d = ((const int*)ei)[E + e];
            }
            int pos = atomicAdd(&gCount[d], 1);
            gSlot[(size_t)d * SLOTS + pos] = make_int2(s, __float_as_int(ew[e]));
        }
    }
}

// ------------- tiny: WcH = fp16(W1 @ W2) (256x64), c = b1 @ W2 (64) -------------
__global__ void combine_weights(const float* __restrict__ W1,
                                const float* __restrict__ b1,
                                const float* __restrict__ W2)
{
    int idx = blockIdx.x * blockDim.x + threadIdx.x;
    if (idx < IN_DIM * OUT_DIM) {
        int i = idx >> 6, j = idx & 63;
        float s = 0.0f;
        const float* w1r = W1 + (size_t)i * H_DIM;
#pragma unroll 8
        for (int k = 0; k < H_DIM; k++)
            s += w1r[k] * W2[(size_t)k * OUT_DIM + j];
        gWcH[idx] = __float2half_rn(s);
    } else if (idx < IN_DIM * OUT_DIM + OUT_DIM) {
        int j = idx - IN_DIM * OUT_DIM;
        float s = 0.0f;
#pragma unroll 8
        for (int k = 0; k < H_DIM; k++)
            s += b1[k] * W2[(size_t)k * OUT_DIM + j];
        gC[j] = s;
    }
}

// ------------- tensor-core GEMM: X0[M,64] = fp16(A[M,256]) @ WcH[256,64] -------------
// (verbatim from R11 — numerically verified)
__global__ void __launch_bounds__(256) gemm_mma(int M,
                                                const float* __restrict__ A,
                                                const __half* __restrict__ Bh,
                                                __half* __restrict__ Ch)
{
    __shared__ __half As[128][72];
    __shared__ __half Bs[64][72];

    const int tid  = threadIdx.x;
    const int wid  = tid >> 5;
    const int lane = tid & 31;
    const int rowBase = blockIdx.x * 128;

    float acc[8][4];
#pragma unroll
    for (int n = 0; n < 8; n++)
#pragma unroll
        for (int j = 0; j < 4; j++) acc[n][j] = 0.0f;

    for (int c = 0; c < IN_DIM / 64; c++) {
        __syncthreads();
#pragma unroll
        for (int i = 0; i < 8; i++) {
            int idx = tid + i * 256;
            int r = idx >> 4, cv = idx & 15;
            int grow = rowBase + r;
            float4 v = make_float4(0.f, 0.f, 0.f, 0.f);
            if (grow < M)
                v = *reinterpret_cast<const float4*>(A + (size_t)grow * IN_DIM + c * 64 + cv * 4);
            __half2* dst = reinterpret_cast<__half2*>(&As[r][cv * 4]);
            dst[0] = __floats2half2_rn(v.x, v.y);
            dst[1] = __floats2half2_rn(v.z, v.w);
        }
#pragma unroll
        for (int i = 0; i < 2; i++) {
            int idx = tid + i * 256;
            int r = idx >> 3, cv = idx & 7;
            uint4 v = *reinterpret_cast<const uint4*>(Bh + (size_t)(c * 64 + r) * 64 + cv * 8);
            *reinterpret_cast<uint4*>(&Bs[r][cv * 8]) = v;
        }
        __syncthreads();

#pragma unroll
        for (int k0 = 0; k0 < 64; k0 += 16) {
            uint32_t a0, a1, a2, a3;
            {
                uint32_t sa = (uint32_t)__cvta_generic_to_shared(
                    &As[16 * wid + (lane & 15)][k0 + 8 * (lane >> 4)]);
                asm volatile("ldmatrix.sync.aligned.m8n8.x4.shared.b16 {%0,%1,%2,%3}, [%4];"
                             : "=r"(a0), "=r"(a1), "=r"(a2), "=r"(a3) : "r"(sa));
            }
#pragma unroll
            for (int n = 0; n < 8; n++) {
                uint32_t b0, b1;
                uint32_t sb = (uint32_t)__cvta_generic_to_shared(
                    &Bs[k0 + (lane & 15)][n * 8]);
                asm volatile("ldmatrix.sync.aligned.m8n8.x2.trans.shared.b16 {%0,%1}, [%2];"
                             : "=r"(b0), "=r"(b1) : "r"(sb));
                asm volatile("mma.sync.aligned.m16n8k16.row.col.f32.f16.f16.f32 "
                             "{%0,%1,%2,%3}, {%4,%5,%6,%7}, {%8,%9}, {%0,%1,%2,%3};"
                             : "+f"(acc[n][0]), "+f"(acc[n][1]), "+f"(acc[n][2]), "+f"(acc[n][3])
                             : "r"(a0), "r"(a1), "r"(a2), "r"(a3), "r"(b0), "r"(b1));
            }
        }
    }

    int row  = lane >> 2;
    int colp = (lane & 3) * 2;
#pragma unroll
    for (int n = 0; n < 8; n++) {
        int g0 = rowBase + 16 * wid + row;
        if (g0 < M)
            *reinterpret_cast<__half2*>(Ch + (size_t)g0 * 64 + n * 8 + colp) =
                __floats2half2_rn(acc[n][0], acc[n][1]);
        int g1 = g0 + 8;
        if (g1 < M)
            *reinterpret_cast<__half2*>(Ch + (size_t)g1 * 64 + n * 8 + colp) =
                __floats2half2_rn(acc[n][2], acc[n][3]);
    }
}

// ------------- bucket gather prop, occupancy-forced -------------
// out[n,:] = wscale*sum_e w_e*x[src_e,:] + ascale*addv[n,:] + bscale*bias[:]
// One warp per node; lane l owns half2 pair {2l, 2l+1}. fp32 accumulation.
// __launch_bounds__(256, 8): cap regs at 32 -> 64 resident warps/SM (100% occ).
template<bool HALF_OUT>
__global__ void __launch_bounds__(256, 8)
gather64h(const __half2* __restrict__ x,
          void* __restrict__ outv,
          const __half2* __restrict__ addv,  // may be null
          const float* __restrict__ bias,    // fp32[64], may be null
          int N, float wscale, float ascale, float bscale)
{
    int warp = (blockIdx.x * blockDim.x + threadIdx.x) >> 5;
    int lane = threadIdx.x & 31;
    if (warp >= N) return;

    const int2* __restrict__ sl = gSlot + (size_t)warp * SLOTS;
    const int end = gCount[warp];
    int e = 0;

    float ax = 0.f, ay = 0.f;

    for (; e + 3 < end; e += 4) {
        int2 s0 = __ldg(&sl[e]);
        int2 s1 = __ldg(&sl[e + 1]);
        int2 s2 = __ldg(&sl[e + 2]);
        int2 s3 = __ldg(&sl[e + 3]);
        float2 f0 = __half22float2(__ldg(x + (size_t)s0.x * 32 + lane));
        float2 f1 = __half22float2(__ldg(x + (size_t)s1.x * 32 + lane));
        float2 f2 = __half22float2(__ldg(x + (size_t)s2.x * 32 + lane));
        float2 f3 = __half22float2(__ldg(x + (size_t)s3.x * 32 + lane));
        float w0 = __int_as_float(s0.y);
        float w1 = __int_as_float(s1.y);
        float w2 = __int_as_float(s2.y);
        float w3 = __int_as_float(s3.y);
        ax = fmaf(w0, f0.x, ax); ay = fmaf(w0, f0.y, ay);
        ax = fmaf(w1, f1.x, ax); ay = fmaf(w1, f1.y, ay);
        ax = fmaf(w2, f2.x, ax); ay = fmaf(w2, f2.y, ay);
        ax = fmaf(w3, f3.x, ax); ay = fmaf(w3, f3.y, ay);
    }
    for (; e < end; e++) {
        int2 s0 = __ldg(&sl[e]);
        float2 f0 = __half22float2(__ldg(x + (size_t)s0.x * 32 + lane));
        float w0 = __int_as_float(s0.y);
        ax = fmaf(w0, f0.x, ax); ay = fmaf(w0, f0.y, ay);
    }

    float rx = wscale * ax, ry = wscale * ay;
    if (addv) {
        float2 a = __half22float2(__ldg(addv + (size_t)warp * 32 + lane));
        rx = fmaf(ascale, a.x, rx);
        ry = fmaf(ascale, a.y, ry);
    }
    if (bias) {
        float2 b = reinterpret_cast<const float2*>(bias)[lane];
        rx = fmaf(bscale, b.x, rx);
        ry = fmaf(bscale, b.y, ry);
    }
    if (HALF_OUT) {
        reinterpret_cast<__half2*>(outv)[(size_t)warp * 32 + lane] = __floats2half2_rn(rx, ry);
    } else {
        reinterpret_cast<float2*>(outv)[(size_t)warp * 32 + lane] = make_float2(rx, ry);
    }
}

__global__ void fill_tail(float* __restrict__ out, int start, int total)
{
    int i = start + blockIdx.x * blockDim.x + threadIdx.x;
    if (i < total) out[i] = 10.0f;
}

extern "C" void kernel_launch(void* const* d_in, const int* in_sizes, int n_in,
                              void* d_out, int out_size)
{
    const float* features = (const float*)d_in[0];
    const void*  ei       = d_in[1];
    const float* ew       = (const float*)d_in[2];
    const float* W1       = (const float*)d_in[3];
    const float* b1       = (const float*)d_in[4];
    const float* W2       = (const float*)d_in[5];
    const float* b2       = (const float*)d_in[6];
    float*       out      = (float*)d_out;

    const int N = in_sizes[0] / IN_DIM;
    const int E = in_sizes[2];

    __half *X0, *P, *H, *A, *B, *WcH;
    float  *C;
    cudaGetSymbolAddress((void**)&X0,  gX0);
    cudaGetSymbolAddress((void**)&P,   gP);
    cudaGetSymbolAddress((void**)&H,   gH);
    cudaGetSymbolAddress((void**)&A,   gA);
    cudaGetSymbolAddress((void**)&B,   gB);
    cudaGetSymbolAddress((void**)&WcH, gWcH);
    cudaGetSymbolAddress((void**)&C,   gC);
    int* countPtr;
    cudaGetSymbolAddress((void**)&countPtr, gCount);

    // lazily-created side stream + events (host objects only)
    static cudaStream_t sCsr = nullptr;
    static cudaEvent_t  evFork = nullptr, evCsr = nullptr;
    if (!sCsr) {
        cudaStreamCreateWithFlags(&sCsr, cudaStreamNonBlocking);
        cudaEventCreateWithFlags(&evFork, cudaEventDisableTiming);
        cudaEventCreateWithFlags(&evCsr,  cudaEventDisableTiming);
    }

    // ---- fork: bucket build on side stream (single pass; no hist, no scan) ----
    cudaEventRecord(evFork, 0);
    cudaStreamWaitEvent(sCsr, evFork, 0);
    cudaMemsetAsync(countPtr, 0, (size_t)N * sizeof(int), sCsr);
    fill_slots<<<((E + 3) / 4 + 255) / 256, 256, 0, sCsr>>>(ei, ew, E, N);
    cudaEventRecord(evCsr, sCsr);

    // ---- main stream: combined weights + tensor-core GEMM ----
    {
        int tot = IN_DIM * OUT_DIM + OUT_DIM;
        combine_weights<<<(tot + 255) / 256, 256>>>(W1, b1, W2);
    }
    gemm_mma<<<(N + 127) / 128, 256>>>(N, features, WcH, X0);

    // ---- join ----
    cudaStreamWaitEvent(0, evCsr, 0);

    const int gthreads = 256;
    const int wpb = gthreads / 32;
    const int gblocks = (N + wpb - 1) / wpb;
    const float inv = 1.0f / PSCALE;   // 0.25

    // Ps = (prop(X0) + c)/4            [stored scale 4]
    gather64h<true><<<gblocks, gthreads>>>((const __half2*)X0, P, nullptr, C,
                                           N, inv, 0.0f, inv);
    // Hs = (prop(4*Ps) + b2)/16        [stored scale 16]
    gather64h<true><<<gblocks, gthreads>>>((const __half2*)P, H, nullptr, b2,
                                           N, inv, 0.0f, inv * inv);

    // ---- APPNP: y_{k+1} = (0.9/4)*prop(y_k) + (0.1/4^{k+1})*Hs ----
    const __half* xcur = H;
    float hscale = ALPHA_F;
    for (int k = 0; k < K_STEPS; k++) {
        if (k == K_STEPS - 1) {
            const float wfin = (1.0f - ALPHA_F) * 16.0f * 262144.0f;  // 0.9*16*4^9
            const float afin = ALPHA_F * 16.0f;                        // 1.6
            gather64h<false><<<gblocks, gthreads>>>((const __half2*)xcur, out,
                                                    (const __half2*)H, nullptr,
                                                    N, wfin, afin, 0.0f);
        } else {
            hscale *= inv;
            __half* xnext = (k & 1) ? B : A;
            gather64h<true><<<gblocks, gthreads>>>((const __half2*)xcur, xnext,
                                                   (const __half2*)H, nullptr,
                                                   N, (1.0f - ALPHA_F) * inv, hscale, 0.0f);
            xcur = xnext;
        }
    }

    // tail (reference returns (x, 10); fill any extra outputs with 10)
    int tail = out_size - N * OUT_DIM;
    if (tail > 0)
        fill_tail<<<(tail + 255) / 256, 256>>>(out, N * OUT_DIM, out_size);
}

// round 14
// speedup vs baseline: 1.4623x; 1.0235x over previous
#include <cuda_runtime.h>
#include <cuda_fp16.h>
#include <cstdint>

// Problem constants (match reference)
#define NMAX      50000
#define IN_DIM    256
#define H_DIM     128
#define OUT_DIM   64
#define K_STEPS   10
#define ALPHA_F   0.1f

// Scale schedule: every prop divides stored values by 4 (exact, folded into
// fp32 scale constants). x_k true = y_k * (16 * 4^k); H true = Hs * 16.
#define PSCALE    4.0f

// fixed-slot bucket layout: SLOTS edge slots per node (max degree << SLOTS)
#define SLOTS     128

// -------- scratch (no allocation allowed -> device globals) --------
__device__ __half gX0[(size_t)NMAX * OUT_DIM];  // X @ (W1@W2)          (scale 1)
__device__ __half gP [(size_t)NMAX * OUT_DIM];  // (prop(X0)+c)/4       (scale 4)
__device__ __half gH [(size_t)NMAX * OUT_DIM];  // (prop(P)+b2)/16      (scale 16)
__device__ __half gA [(size_t)NMAX * OUT_DIM];  // ping  (scale 16*4^k)
__device__ __half gB [(size_t)NMAX * OUT_DIM];  // pong
__device__ __half gWcH[IN_DIM * OUT_DIM];       // fp16(W1 @ W2)  (256x64)
__device__ float  gC [OUT_DIM];                 // b1 @ W2
// bucket scratch
__device__ int    gCount[NMAX];                 // per-node edge count (atomic wp)
__device__ __align__(16) int2 gSlot[(size_t)NMAX * SLOTS];  // (src, w-bits)

// ------------- per-block dtype detection (uniform across block) -------------
__device__ __forceinline__ bool idx_is64(const void* __restrict__ ei, int N)
{
    const long long* p = (const long long*)ei;
    bool ok = true;
#pragma unroll
    for (int i = 0; i < 16; i++) {
        long long v = p[i];
        ok &= (v >= 0 && v < (long long)N);
    }
    return ok;
}

// ------------- single-pass bucket fill (no hist, no scan) -------------
__global__ void fill_slots(const void* __restrict__ ei, const float* __restrict__ ew,
                           int E, int N)
{
    const bool is64 = idx_is64(ei, N);
    int base = (blockIdx.x * blockDim.x + threadIdx.x) * 4;
    if (base >= E) return;
    if (base + 4 <= E && (E & 3) == 0) {
        int s0, s1, s2, s3, d0, d1, d2, d3;
        if (is64) {
            const long long* ps = (const long long*)ei + base;
            longlong2 a = *reinterpret_cast<const longlong2*>(ps);
            longlong2 b = *reinterpret_cast<const longlong2*>(ps + 2);
            const long long* pd = (const long long*)ei + E + base;
            longlong2 c = *reinterpret_cast<const longlong2*>(pd);
            longlong2 d = *reinterpret_cast<const longlong2*>(pd + 2);
            s0 = (int)a.x; s1 = (int)a.y; s2 = (int)b.x; s3 = (int)b.y;
            d0 = (int)c.x; d1 = (int)c.y; d2 = (int)d.x; d3 = (int)d.y;
        } else {
            int4 sv = *reinterpret_cast<const int4*>((const int*)ei + base);
            int4 dv = *reinterpret_cast<const int4*>((const int*)ei + E + base);
            s0 = sv.x; s1 = sv.y; s2 = sv.z; s3 = sv.w;
            d0 = dv.x; d1 = dv.y; d2 = dv.z; d3 = dv.w;
        }
        float4 wv = *reinterpret_cast<const float4*>(ew + base);
        int p0 = atomicAdd(&gCount[d0], 1);
        gSlot[(size_t)d0 * SLOTS + p0] = make_int2(s0, __float_as_int(wv.x));
        int p1 = atomicAdd(&gCount[d1], 1);
        gSlot[(size_t)d1 * SLOTS + p1] = make_int2(s1, __float_as_int(wv.y));
        int p2 = atomicAdd(&gCount[d2], 1);
        gSlot[(size_t)d2 * SLOTS + p2] = make_int2(s2, __float_as_int(wv.z));
        int p3 = atomicAdd(&gCount[d3], 1);
        gSlot[(size_t)d3 * SLOTS + p3] = make_int2(s3, __float_as_int(wv.w));
    } else {
        for (int e = base; e < min(base + 4, E); e++) {
            int s, d;
            if (is64) {
                s = (int)((const long long*)ei)[e];
                d = (int)((const long long*)ei)[E + e];
            } else {
                s = ((const int*)ei)[e];
                d = ((const int*)ei)[E + e];
            }
            int pos = atomicAdd(&gCount[d], 1);
            gSlot[(size_t)d * SLOTS + pos] = make_int2(s, __float_as_int(ew[e]));
        }
    }
}

// ------------- tiny: WcH = fp16(W1 @ W2) (256x64), c = b1 @ W2 (64) -------------
// float4 W1-row loads + 4 independent partials; fully unrolled for MLP.
__global__ void combine_weights(const float* __restrict__ W1,
                                const float* __restrict__ b1,
                                const float* __restrict__ W2)
{
    int idx = blockIdx.x * blockDim.x + threadIdx.x;
    if (idx < IN_DIM * OUT_DIM) {
        int i = idx >> 6, j = idx & 63;
        const float4* w1r = reinterpret_cast<const float4*>(W1 + (size_t)i * H_DIM);
        float s0 = 0.f, s1 = 0.f, s2 = 0.f, s3 = 0.f;
#pragma unroll
        for (int k4 = 0; k4 < H_DIM / 4; k4++) {
            float4 a = __ldg(&w1r[k4]);
            int k = k4 * 4;
            s0 = fmaf(a.x, __ldg(&W2[(size_t)(k + 0) * OUT_DIM + j]), s0);
            s1 = fmaf(a.y, __ldg(&W2[(size_t)(k + 1) * OUT_DIM + j]), s1);
            s2 = fmaf(a.z, __ldg(&W2[(size_t)(k + 2) * OUT_DIM + j]), s2);
            s3 = fmaf(a.w, __ldg(&W2[(size_t)(k + 3) * OUT_DIM + j]), s3);
        }
        gWcH[idx] = __float2half_rn((s0 + s1) + (s2 + s3));
    } else if (idx < IN_DIM * OUT_DIM + OUT_DIM) {
        int j = idx - IN_DIM * OUT_DIM;
        float s = 0.0f;
#pragma unroll 8
        for (int k = 0; k < H_DIM; k++)
            s += b1[k] * W2[(size_t)k * OUT_DIM + j];
        gC[j] = s;
    }
}

// ------------- tensor-core GEMM: X0[M,64] = fp16(A[M,256]) @ WcH[256,64] -------------
// (verbatim from R11 — numerically verified)
__global__ void __launch_bounds__(256) gemm_mma(int M,
                                                const float* __restrict__ A,
                                                const __half* __restrict__ Bh,
                                                __half* __restrict__ Ch)
{
    __shared__ __half As[128][72];
    __shared__ __half Bs[64][72];

    const int tid  = threadIdx.x;
    const int wid  = tid >> 5;
    const int lane = tid & 31;
    const int rowBase = blockIdx.x * 128;

    float acc[8][4];
#pragma unroll
    for (int n = 0; n < 8; n++)
#pragma unroll
        for (int j = 0; j < 4; j++) acc[n][j] = 0.0f;

    for (int c = 0; c < IN_DIM / 64; c++) {
        __syncthreads();
#pragma unroll
        for (int i = 0; i < 8; i++) {
            int idx = tid + i * 256;
            int r = idx >> 4, cv = idx & 15;
            int grow = rowBase + r;
            float4 v = make_float4(0.f, 0.f, 0.f, 0.f);
            if (grow < M)
                v = *reinterpret_cast<const float4*>(A + (size_t)grow * IN_DIM + c * 64 + cv * 4);
            __half2* dst = reinterpret_cast<__half2*>(&As[r][cv * 4]);
            dst[0] = __floats2half2_rn(v.x, v.y);
            dst[1] = __floats2half2_rn(v.z, v.w);
        }
#pragma unroll
        for (int i = 0; i < 2; i++) {
            int idx = tid + i * 256;
            int r = idx >> 3, cv = idx & 7;
            uint4 v = *reinterpret_cast<const uint4*>(Bh + (size_t)(c * 64 + r) * 64 + cv * 8);
            *reinterpret_cast<uint4*>(&Bs[r][cv * 8]) = v;
        }
        __syncthreads();

#pragma unroll
        for (int k0 = 0; k0 < 64; k0 += 16) {
            uint32_t a0, a1, a2, a3;
            {
                uint32_t sa = (uint32_t)__cvta_generic_to_shared(
                    &As[16 * wid + (lane & 15)][k0 + 8 * (lane >> 4)]);
                asm volatile("ldmatrix.sync.aligned.m8n8.x4.shared.b16 {%0,%1,%2,%3}, [%4];"
                             : "=r"(a0), "=r"(a1), "=r"(a2), "=r"(a3) : "r"(sa));
            }
#pragma unroll
            for (int n = 0; n < 8; n++) {
                uint32_t b0, b1;
                uint32_t sb = (uint32_t)__cvta_generic_to_shared(
                    &Bs[k0 + (lane & 15)][n * 8]);
                asm volatile("ldmatrix.sync.aligned.m8n8.x2.trans.shared.b16 {%0,%1}, [%2];"
                             : "=r"(b0), "=r"(b1) : "r"(sb));
                asm volatile("mma.sync.aligned.m16n8k16.row.col.f32.f16.f16.f32 "
                             "{%0,%1,%2,%3}, {%4,%5,%6,%7}, {%8,%9}, {%0,%1,%2,%3};"
                             : "+f"(acc[n][0]), "+f"(acc[n][1]), "+f"(acc[n][2]), "+f"(acc[n][3])
                             : "r"(a0), "r"(a1), "r"(a2), "r"(a3), "r"(b0), "r"(b1));
            }
        }
    }

    int row  = lane >> 2;
    int colp = (lane & 3) * 2;
#pragma unroll
    for (int n = 0; n < 8; n++) {
        int g0 = rowBase + 16 * wid + row;
        if (g0 < M)
            *reinterpret_cast<__half2*>(Ch + (size_t)g0 * 64 + n * 8 + colp) =
                __floats2half2_rn(acc[n][0], acc[n][1]);
        int g1 = g0 + 8;
        if (g1 < M)
            *reinterpret_cast<__half2*>(Ch + (size_t)g1 * 64 + n * 8 + colp) =
                __floats2half2_rn(acc[n][2], acc[n][3]);
    }
}

// ------------- bucket gather prop, occ-forced + int4 slot loads -------------
// out[n,:] = wscale*sum_e w_e*x[src_e,:] + ascale*addv[n,:] + bscale*bias[:]
// One warp per node; lane l owns half2 pair {2l, 2l+1}. fp32 accumulation.
// Slot base is 1024B-aligned and e stays even -> int4 loads always aligned.
template<bool HALF_OUT>
__global__ void __launch_bounds__(256, 8)
gather64h(const __half2* __restrict__ x,
          void* __restrict__ outv,
          const __half2* __restrict__ addv,  // may be null
          const float* __restrict__ bias,    // fp32[64], may be null
          int N, float wscale, float ascale, float bscale)
{
    int warp = (blockIdx.x * blockDim.x + threadIdx.x) >> 5;
    int lane = threadIdx.x & 31;
    if (warp >= N) return;

    const int4* __restrict__ sl4 =
        reinterpret_cast<const int4*>(gSlot + (size_t)warp * SLOTS);
    const int end = gCount[warp];
    int e = 0;

    float ax = 0.f, ay = 0.f;

    // 4 edges per iter: 2 int4 slot loads + 4 row loads in flight
    for (; e + 3 < end; e += 4) {
        int4 c0 = __ldg(&sl4[(e >> 1)]);
        int4 c1 = __ldg(&sl4[(e >> 1) + 1]);
        float2 f0 = __half22float2(__ldg(x + (size_t)c0.x * 32 + lane));
        float2 f1 = __half22float2(__ldg(x + (size_t)c0.z * 32 + lane));
        float2 f2 = __half22float2(__ldg(x + (size_t)c1.x * 32 + lane));
        float2 f3 = __half22float2(__ldg(x + (size_t)c1.z * 32 + lane));
        float w0 = __int_as_float(c0.y);
        float w1 = __int_as_float(c0.w);
        float w2 = __int_as_float(c1.y);
        float w3 = __int_as_float(c1.w);
        ax = fmaf(w0, f0.x, ax); ay = fmaf(w0, f0.y, ay);
        ax = fmaf(w1, f1.x, ax); ay = fmaf(w1, f1.y, ay);
        ax = fmaf(w2, f2.x, ax); ay = fmaf(w2, f2.y, ay);
        ax = fmaf(w3, f3.x, ax); ay = fmaf(w3, f3.y, ay);
    }
    // 2 edges
    for (; e + 1 < end; e += 2) {
        int4 c0 = __ldg(&sl4[(e >> 1)]);
        float2 f0 = __half22float2(__ldg(x + (size_t)c0.x * 32 + lane));
        float2 f1 = __half22float2(__ldg(x + (size_t)c0.z * 32 + lane));
        float w0 = __int_as_float(c0.y);
        float w1 = __int_as_float(c0.w);
        ax = fmaf(w0, f0.x, ax); ay = fmaf(w0, f0.y, ay);
        ax = fmaf(w1, f1.x, ax); ay = fmaf(w1, f1.y, ay);
    }
    // tail single
    if (e < end) {
        int2 s0 = __ldg(&gSlot[(size_t)warp * SLOTS + e]);
        float2 f0 = __half22float2(__ldg(x + (size_t)s0.x * 32 + lane));
        float w0 = __int_as_float(s0.y);
        ax = fmaf(w0, f0.x, ax); ay = fmaf(w0, f0.y, ay);
    }

    float rx = wscale * ax, ry = wscale * ay;
    if (addv) {
        float2 a = __half22float2(__ldg(addv + (size_t)warp * 32 + lane));
        rx = fmaf(ascale, a.x, rx);
        ry = fmaf(ascale, a.y, ry);
    }
    if (bias) {
        float2 b = reinterpret_cast<const float2*>(bias)[lane];
        rx = fmaf(bscale, b.x, rx);
        ry = fmaf(bscale, b.y, ry);
    }
    if (HALF_OUT) {
        reinterpret_cast<__half2*>(outv)[(size_t)warp * 32 + lane] = __floats2half2_rn(rx, ry);
    } else {
        reinterpret_cast<float2*>(outv)[(size_t)warp * 32 + lane] = make_float2(rx, ry);
    }
}

__global__ void fill_tail(float* __restrict__ out, int start, int total)
{
    int i = start + blockIdx.x * blockDim.x + threadIdx.x;
    if (i < total) out[i] = 10.0f;
}

extern "C" void kernel_launch(void* const* d_in, const int* in_sizes, int n_in,
                              void* d_out, int out_size)
{
    const float* features = (const float*)d_in[0];
    const void*  ei       = d_in[1];
    const float* ew       = (const float*)d_in[2];
    const float* W1       = (const float*)d_in[3];
    const float* b1       = (const float*)d_in[4];
    const float* W2       = (const float*)d_in[5];
    const float* b2       = (const float*)d_in[6];
    float*       out      = (float*)d_out;

    const int N = in_sizes[0] / IN_DIM;
    const int E = in_sizes[2];

    __half *X0, *P, *H, *A, *B, *WcH;
    float  *C;
    cudaGetSymbolAddress((void**)&X0,  gX0);
    cudaGetSymbolAddress((void**)&P,   gP);
    cudaGetSymbolAddress((void**)&H,   gH);
    cudaGetSymbolAddress((void**)&A,   gA);
    cudaGetSymbolAddress((void**)&B,   gB);
    cudaGetSymbolAddress((void**)&WcH, gWcH);
    cudaGetSymbolAddress((void**)&C,   gC);
    int* countPtr;
    cudaGetSymbolAddress((void**)&countPtr, gCount);

    // lazily-created side stream + events (host objects only)
    static cudaStream_t sCsr = nullptr;
    static cudaEvent_t  evFork = nullptr, evCsr = nullptr;
    if (!sCsr) {
        cudaStreamCreateWithFlags(&sCsr, cudaStreamNonBlocking);
        cudaEventCreateWithFlags(&evFork, cudaEventDisableTiming);
        cudaEventCreateWithFlags(&evCsr,  cudaEventDisableTiming);
    }

    // ---- fork: bucket build on side stream (single pass; no hist, no scan) ----
    cudaEventRecord(evFork, 0);
    cudaStreamWaitEvent(sCsr, evFork, 0);
    cudaMemsetAsync(countPtr, 0, (size_t)N * sizeof(int), sCsr);
    fill_slots<<<((E + 3) / 4 + 255) / 256, 256, 0, sCsr>>>(ei, ew, E, N);
    cudaEventRecord(evCsr, sCsr);

    // ---- main stream: combined weights + tensor-core GEMM ----
    {
        int tot = IN_DIM * OUT_DIM + OUT_DIM;
        combine_weights<<<(tot + 255) / 256, 256>>>(W1, b1, W2);
    }
    gemm_mma<<<(N + 127) / 128, 256>>>(N, features, WcH, X0);

    // ---- join ----
    cudaStreamWaitEvent(0, evCsr, 0);

    const int gthreads = 256;
    const int wpb = gthreads / 32;
    const int gblocks = (N + wpb - 1) / wpb;
    const float inv = 1.0f / PSCALE;   // 0.25

    // Ps = (prop(X0) + c)/4            [stored scale 4]
    gather64h<true><<<gblocks, gthreads>>>((const __half2*)X0, P, nullptr, C,
                                           N, inv, 0.0f, inv);
    // Hs = (prop(4*Ps) + b2)/16        [stored scale 16]
    gather64h<true><<<gblocks, gthreads>>>((const __half2*)P, H, nullptr, b2,
                                           N, inv, 0.0f, inv * inv);

    // ---- APPNP: y_{k+1} = (0.9/4)*prop(y_k) + (0.1/4^{k+1})*Hs ----
    const __half* xcur = H;
    float hscale = ALPHA_F;
    for (int k = 0; k < K_STEPS; k++) {
        if (k == K_STEPS - 1) {
            const float wfin = (1.0f - ALPHA_F) * 16.0f * 262144.0f;  // 0.9*16*4^9
            const float afin = ALPHA_F * 16.0f;                        // 1.6
            gather64h<false><<<gblocks, gthreads>>>((const __half2*)xcur, out,
                                                    (const __half2*)H, nullptr,
                                                    N, wfin, afin, 0.0f);
        } else {
            hscale *= inv;
            __half* xnext = (k & 1) ? B : A;
            gather64h<true><<<gblocks, gthreads>>>((const __half2*)xcur, xnext,
                                                   (const __half2*)H, nullptr,
                                                   N, (1.0f - ALPHA_F) * inv, hscale, 0.0f);
            xcur = xnext;
        }
    }

    // tail (reference returns (x, 10); fill any extra outputs with 10)
    int tail = out_size - N * OUT_DIM;
    if (tail > 0)
        fill_tail<<<(tail + 255) / 256, 256>>>(out, N * OUT_DIM, out_size);
}

// round 15
// speedup vs baseline: 1.4949x; 1.0223x over previous
#include <cuda_runtime.h>
#include <cuda_fp16.h>
#include <cstdint>

// Problem constants (match reference)
#define NMAX      50000
#define IN_DIM    256
#define H_DIM     128
#define OUT_DIM   64
#define K_STEPS   10
#define ALPHA_F   0.1f

// Scale schedule: every prop divides stored values by 4 (exact, folded into
// fp32 scale constants). x_k true = y_k * (16 * 4^k); H true = Hs * 16.
#define PSCALE    4.0f

// fixed-slot bucket layout: SLOTS edge slots per node (max degree << SLOTS)
#define SLOTS     128

// -------- scratch (no allocation allowed -> device globals) --------
__device__ __half gX0[(size_t)NMAX * OUT_DIM];  // X @ (W1@W2)          (scale 1)
__device__ __half gP [(size_t)NMAX * OUT_DIM];  // (prop(X0)+c)/4       (scale 4)
__device__ __half gH [(size_t)NMAX * OUT_DIM];  // (prop(P)+b2)/16      (scale 16)
__device__ __half gA [(size_t)NMAX * OUT_DIM];  // ping  (scale 16*4^k)
__device__ __half gB [(size_t)NMAX * OUT_DIM];  // pong
__device__ __half gWcH[IN_DIM * OUT_DIM];       // fp16(W1 @ W2)  (256x64)
__device__ float  gC [OUT_DIM];                 // b1 @ W2
// bucket scratch: packed edge = src (low 16) | fp16 weight bits (high 16)
__device__ int    gCount[NMAX];                 // per-node edge count (atomic wp)
__device__ __align__(16) unsigned int gSlotP[(size_t)NMAX * SLOTS];

// ------------- per-block dtype detection (uniform across block) -------------
__device__ __forceinline__ bool idx_is64(const void* __restrict__ ei, int N)
{
    const long long* p = (const long long*)ei;
    bool ok = true;
#pragma unroll
    for (int i = 0; i < 16; i++) {
        long long v = p[i];
        ok &= (v >= 0 && v < (long long)N);
    }
    return ok;
}

// decode packed edge
__device__ __forceinline__ void decode_edge(unsigned int v, int& src, float& w)
{
    src = (int)(v & 0xffffu);
    w = __half2float(__ushort_as_half((unsigned short)(v >> 16)));
}

// ------------- single-pass bucket fill (no hist, no scan) -------------
__global__ void fill_slots(const void* __restrict__ ei, const float* __restrict__ ew,
                           int E, int N)
{
    const bool is64 = idx_is64(ei, N);
    int base = (blockIdx.x * blockDim.x + threadIdx.x) * 4;
    if (base >= E) return;
    if (base + 4 <= E && (E & 3) == 0) {
        int s0, s1, s2, s3, d0, d1, d2, d3;
        if (is64) {
            const long long* ps = (const long long*)ei + base;
            longlong2 a = *reinterpret_cast<const longlong2*>(ps);
            longlong2 b = *reinterpret_cast<const longlong2*>(ps + 2);
            const long long* pd = (const long long*)ei + E + base;
            longlong2 c = *reinterpret_cast<const longlong2*>(pd);
            longlong2 d = *reinterpret_cast<const longlong2*>(pd + 2);
            s0 = (int)a.x; s1 = (int)a.y; s2 = (int)b.x; s3 = (int)b.y;
            d0 = (int)c.x; d1 = (int)c.y; d2 = (int)d.x; d3 = (int)d.y;
        } else {
            int4 sv = *reinterpret_cast<const int4*>((const int*)ei + base);
            int4 dv = *reinterpret_cast<const int4*>((const int*)ei + E + base);
            s0 = sv.x; s1 = sv.y; s2 = sv.z; s3 = sv.w;
            d0 = dv.x; d1 = dv.y; d2 = dv.z; d3 = dv.w;
        }
        float4 wv = *reinterpret_cast<const float4*>(ew + base);
        unsigned int w0 = (unsigned int)__half_as_ushort(__float2half_rn(wv.x)) << 16;
        unsigned int w1 = (unsigned int)__half_as_ushort(__float2half_rn(wv.y)) << 16;
        unsigned int w2 = (unsigned int)__half_as_ushort(__float2half_rn(wv.z)) << 16;
        unsigned int w3 = (unsigned int)__half_as_ushort(__float2half_rn(wv.w)) << 16;
        int p0 = atomicAdd(&gCount[d0], 1);
        gSlotP[(size_t)d0 * SLOTS + p0] = (unsigned int)s0 | w0;
        int p1 = atomicAdd(&gCount[d1], 1);
        gSlotP[(size_t)d1 * SLOTS + p1] = (unsigned int)s1 | w1;
        int p2 = atomicAdd(&gCount[d2], 1);
        gSlotP[(size_t)d2 * SLOTS + p2] = (unsigned int)s2 | w2;
        int p3 = atomicAdd(&gCount[d3], 1);
        gSlotP[(size_t)d3 * SLOTS + p3] = (unsigned int)s3 | w3;
    } else {
        for (int e = base; e < min(base + 4, E); e++) {
            int s, d;
            if (is64) {
                s = (int)((const long long*)ei)[e];
                d = (int)((const long long*)ei)[E + e];
            } else {
                s = ((const int*)ei)[e];
                d = ((const int*)ei)[E + e];
            }
            unsigned int wb = (unsigned int)__half_as_ushort(__float2half_rn(ew[e])) << 16;
            int pos = atomicAdd(&gCount[d], 1);
            gSlotP[(size_t)d * SLOTS + pos] = (unsigned int)s | wb;
        }
    }
}

// ------------- tiny: WcH = fp16(W1 @ W2) (256x64), c = b1 @ W2 (64) -------------
__global__ void combine_weights(const float* __restrict__ W1,
                                const float* __restrict__ b1,
                                const float* __restrict__ W2)
{
    int idx = blockIdx.x * blockDim.x + threadIdx.x;
    if (idx < IN_DIM * OUT_DIM) {
        int i = idx >> 6, j = idx & 63;
        const float4* w1r = reinterpret_cast<const float4*>(W1 + (size_t)i * H_DIM);
        float s0 = 0.f, s1 = 0.f, s2 = 0.f, s3 = 0.f;
#pragma unroll
        for (int k4 = 0; k4 < H_DIM / 4; k4++) {
            float4 a = __ldg(&w1r[k4]);
            int k = k4 * 4;
            s0 = fmaf(a.x, __ldg(&W2[(size_t)(k + 0) * OUT_DIM + j]), s0);
            s1 = fmaf(a.y, __ldg(&W2[(size_t)(k + 1) * OUT_DIM + j]), s1);
            s2 = fmaf(a.z, __ldg(&W2[(size_t)(k + 2) * OUT_DIM + j]), s2);
            s3 = fmaf(a.w, __ldg(&W2[(size_t)(k + 3) * OUT_DIM + j]), s3);
        }
        gWcH[idx] = __float2half_rn((s0 + s1) + (s2 + s3));
    } else if (idx < IN_DIM * OUT_DIM + OUT_DIM) {
        int j = idx - IN_DIM * OUT_DIM;
        float s = 0.0f;
#pragma unroll 8
        for (int k = 0; k < H_DIM; k++)
            s += b1[k] * W2[(size_t)k * OUT_DIM + j];
        gC[j] = s;
    }
}

// ------------- tensor-core GEMM: X0[M,64] = fp16(A[M,256]) @ WcH[256,64] -------------
// (verbatim from R11 — numerically verified)
__global__ void __launch_bounds__(256) gemm_mma(int M,
                                                const float* __restrict__ A,
                                                const __half* __restrict__ Bh,
                                                __half* __restrict__ Ch)
{
    __shared__ __half As[128][72];
    __shared__ __half Bs[64][72];

    const int tid  = threadIdx.x;
    const int wid  = tid >> 5;
    const int lane = tid & 31;
    const int rowBase = blockIdx.x * 128;

    float acc[8][4];
#pragma unroll
    for (int n = 0; n < 8; n++)
#pragma unroll
        for (int j = 0; j < 4; j++) acc[n][j] = 0.0f;

    for (int c = 0; c < IN_DIM / 64; c++) {
        __syncthreads();
#pragma unroll
        for (int i = 0; i < 8; i++) {
            int idx = tid + i * 256;
            int r = idx >> 4, cv = idx & 15;
            int grow = rowBase + r;
            float4 v = make_float4(0.f, 0.f, 0.f, 0.f);
            if (grow < M)
                v = *reinterpret_cast<const float4*>(A + (size_t)grow * IN_DIM + c * 64 + cv * 4);
            __half2* dst = reinterpret_cast<__half2*>(&As[r][cv * 4]);
            dst[0] = __floats2half2_rn(v.x, v.y);
            dst[1] = __floats2half2_rn(v.z, v.w);
        }
#pragma unroll
        for (int i = 0; i < 2; i++) {
            int idx = tid + i * 256;
            int r = idx >> 3, cv = idx & 7;
            uint4 v = *reinterpret_cast<const uint4*>(Bh + (size_t)(c * 64 + r) * 64 + cv * 8);
            *reinterpret_cast<uint4*>(&Bs[r][cv * 8]) = v;
        }
        __syncthreads();

#pragma unroll
        for (int k0 = 0; k0 < 64; k0 += 16) {
            uint32_t a0, a1, a2, a3;
            {
                uint32_t sa = (uint32_t)__cvta_generic_to_shared(
                    &As[16 * wid + (lane & 15)][k0 + 8 * (lane >> 4)]);
                asm volatile("ldmatrix.sync.aligned.m8n8.x4.shared.b16 {%0,%1,%2,%3}, [%4];"
                             : "=r"(a0), "=r"(a1), "=r"(a2), "=r"(a3) : "r"(sa));
            }
#pragma unroll
            for (int n = 0; n < 8; n++) {
                uint32_t b0, b1;
                uint32_t sb = (uint32_t)__cvta_generic_to_shared(
                    &Bs[k0 + (lane & 15)][n * 8]);
                asm volatile("ldmatrix.sync.aligned.m8n8.x2.trans.shared.b16 {%0,%1}, [%2];"
                             : "=r"(b0), "=r"(b1) : "r"(sb));
                asm volatile("mma.sync.aligned.m16n8k16.row.col.f32.f16.f16.f32 "
                             "{%0,%1,%2,%3}, {%4,%5,%6,%7}, {%8,%9}, {%0,%1,%2,%3};"
                             : "+f"(acc[n][0]), "+f"(acc[n][1]), "+f"(acc[n][2]), "+f"(acc[n][3])
                             : "r"(a0), "r"(a1), "r"(a2), "r"(a3), "r"(b0), "r"(b1));
            }
        }
    }

    int row  = lane >> 2;
    int colp = (lane & 3) * 2;
#pragma unroll
    for (int n = 0; n < 8; n++) {
        int g0 = rowBase + 16 * wid + row;
        if (g0 < M)
            *reinterpret_cast<__half2*>(Ch + (size_t)g0 * 64 + n * 8 + colp) =
                __floats2half2_rn(acc[n][0], acc[n][1]);
        int g1 = g0 + 8;
        if (g1 < M)
            *reinterpret_cast<__half2*>(Ch + (size_t)g1 * 64 + n * 8 + colp) =
                __floats2half2_rn(acc[n][2], acc[n][3]);
    }
}

// ------------- bucket gather prop: packed 4B edges, 8-edge MLP, occ-forced -------------
// out[n,:] = wscale*sum_e w_e*x[src_e,:] + ascale*addv[n,:] + bscale*bias[:]
// One warp per node; lane l owns half2 pair {2l, 2l+1}. fp32 accumulation.
// 8-edge body: 2 uint4 slot loads + 8 row loads in flight per warp.
template<bool HALF_OUT>
__global__ void __launch_bounds__(256, 8)
gather64h(const __half2* __restrict__ x,
          void* __restrict__ outv,
          const __half2* __restrict__ addv,  // may be null
          const float* __restrict__ bias,    // fp32[64], may be null
          int N, float wscale, float ascale, float bscale)
{
    int warp = (blockIdx.x * blockDim.x + threadIdx.x) >> 5;
    int lane = threadIdx.x & 31;
    if (warp >= N) return;

    const unsigned int* __restrict__ sl = gSlotP + (size_t)warp * SLOTS;
    const int end = gCount[warp];
    int e = 0;

    float ax = 0.f, ay = 0.f;

    // 8 edges per iter: 2 uint4 slot loads + 8 row loads in flight
    for (; e + 7 < end; e += 8) {
        uint4 c0 = __ldg(reinterpret_cast<const uint4*>(sl + e));
        uint4 c1 = __ldg(reinterpret_cast<const uint4*>(sl + e + 4));
        int s0, s1, s2, s3, s4, s5, s6, s7;
        float w0, w1, w2, w3, w4, w5, w6, w7;
        decode_edge(c0.x, s0, w0); decode_edge(c0.y, s1, w1);
        decode_edge(c0.z, s2, w2); decode_edge(c0.w, s3, w3);
        decode_edge(c1.x, s4, w4); decode_edge(c1.y, s5, w5);
        decode_edge(c1.z, s6, w6); decode_edge(c1.w, s7, w7);
        float2 f0 = __half22float2(__ldg(x + (size_t)s0 * 32 + lane));
        float2 f1 = __half22float2(__ldg(x + (size_t)s1 * 32 + lane));
        float2 f2 = __half22float2(__ldg(x + (size_t)s2 * 32 + lane));
        float2 f3 = __half22float2(__ldg(x + (size_t)s3 * 32 + lane));
        float2 f4 = __half22float2(__ldg(x + (size_t)s4 * 32 + lane));
        float2 f5 = __half22float2(__ldg(x + (size_t)s5 * 32 + lane));
        float2 f6 = __half22float2(__ldg(x + (size_t)s6 * 32 + lane));
        float2 f7 = __half22float2(__ldg(x + (size_t)s7 * 32 + lane));
        ax = fmaf(w0, f0.x, ax); ay = fmaf(w0, f0.y, ay);
        ax = fmaf(w1, f1.x, ax); ay = fmaf(w1, f1.y, ay);
        ax = fmaf(w2, f2.x, ax); ay = fmaf(w2, f2.y, ay);
        ax = fmaf(w3, f3.x, ax); ay = fmaf(w3, f3.y, ay);
        ax = fmaf(w4, f4.x, ax); ay = fmaf(w4, f4.y, ay);
        ax = fmaf(w5, f5.x, ax); ay = fmaf(w5, f5.y, ay);
        ax = fmaf(w6, f6.x, ax); ay = fmaf(w6, f6.y, ay);
        ax = fmaf(w7, f7.x, ax); ay = fmaf(w7, f7.y, ay);
    }
    // 4 edges
    for (; e + 3 < end; e += 4) {
        uint4 c0 = __ldg(reinterpret_cast<const uint4*>(sl + e));
        int s0, s1, s2, s3;
        float w0, w1, w2, w3;
        decode_edge(c0.x, s0, w0); decode_edge(c0.y, s1, w1);
        decode_edge(c0.z, s2, w2); decode_edge(c0.w, s3, w3);
        float2 f0 = __half22float2(__ldg(x + (size_t)s0 * 32 + lane));
        float2 f1 = __half22float2(__ldg(x + (size_t)s1 * 32 + lane));
        float2 f2 = __half22float2(__ldg(x + (size_t)s2 * 32 + lane));
        float2 f3 = __half22float2(__ldg(x + (size_t)s3 * 32 + lane));
        ax = fmaf(w0, f0.x, ax); ay = fmaf(w0, f0.y, ay);
        ax = fmaf(w1, f1.x, ax); ay = fmaf(w1, f1.y, ay);
        ax = fmaf(w2, f2.x, ax); ay = fmaf(w2, f2.y, ay);
        ax = fmaf(w3, f3.x, ax); ay = fmaf(w3, f3.y, ay);
    }
    // tail
    for (; e < end; e++) {
        unsigned int v = __ldg(&sl[e]);
        int s0; float w0;
        decode_edge(v, s0, w0);
        float2 f0 = __half22float2(__ldg(x + (size_t)s0 * 32 + lane));
        ax = fmaf(w0, f0.x, ax); ay = fmaf(w0, f0.y, ay);
    }

    float rx = wscale * ax, ry = wscale * ay;
    if (addv) {
        float2 a = __half22float2(__ldg(addv + (size_t)warp * 32 + lane));
        rx = fmaf(ascale, a.x, rx);
        ry = fmaf(ascale, a.y, ry);
    }
    if (bias) {
        float2 b = reinterpret_cast<const float2*>(bias)[lane];
        rx = fmaf(bscale, b.x, rx);
        ry = fmaf(bscale, b.y, ry);
    }
    if (HALF_OUT) {
        reinterpret_cast<__half2*>(outv)[(size_t)warp * 32 + lane] = __floats2half2_rn(rx, ry);
    } else {
        reinterpret_cast<float2*>(outv)[(size_t)warp * 32 + lane] = make_float2(rx, ry);
    }
}

__global__ void fill_tail(float* __restrict__ out, int start, int total)
{
    int i = start + blockIdx.x * blockDim.x + threadIdx.x;
    if (i < total) out[i] = 10.0f;
}

extern "C" void kernel_launch(void* const* d_in, const int* in_sizes, int n_in,
                              void* d_out, int out_size)
{
    const float* features = (const float*)d_in[0];
    const void*  ei       = d_in[1];
    const float* ew       = (const float*)d_in[2];
    const float* W1       = (const float*)d_in[3];
    const float* b1       = (const float*)d_in[4];
    const float* W2       = (const float*)d_in[5];
    const float* b2       = (const float*)d_in[6];
    float*       out      = (float*)d_out;

    const int N = in_sizes[0] / IN_DIM;
    const int E = in_sizes[2];

    __half *X0, *P, *H, *A, *B, *WcH;
    float  *C;
    cudaGetSymbolAddress((void**)&X0,  gX0);
    cudaGetSymbolAddress((void**)&P,   gP);
    cudaGetSymbolAddress((void**)&H,   gH);
    cudaGetSymbolAddress((void**)&A,   gA);
    cudaGetSymbolAddress((void**)&B,   gB);
    cudaGetSymbolAddress((void**)&WcH, gWcH);
    cudaGetSymbolAddress((void**)&C,   gC);
    int* countPtr;
    cudaGetSymbolAddress((void**)&countPtr, gCount);

    // lazily-created side stream + events (host objects only)
    static cudaStream_t sCsr = nullptr;
    static cudaEvent_t  evFork = nullptr, evCsr = nullptr;
    if (!sCsr) {
        cudaStreamCreateWithFlags(&sCsr, cudaStreamNonBlocking);
        cudaEventCreateWithFlags(&evFork, cudaEventDisableTiming);
        cudaEventCreateWithFlags(&evCsr,  cudaEventDisableTiming);
    }

    // ---- fork: bucket build on side stream (single pass; no hist, no scan) ----
    cudaEventRecord(evFork, 0);
    cudaStreamWaitEvent(sCsr, evFork, 0);
    cudaMemsetAsync(countPtr, 0, (size_t)N * sizeof(int), sCsr);
    fill_slots<<<((E + 3) / 4 + 255) / 256, 256, 0, sCsr>>>(ei, ew, E, N);
    cudaEventRecord(evCsr, sCsr);

    // ---- main stream: combined weights + tensor-core GEMM ----
    {
        int tot = IN_DIM * OUT_DIM + OUT_DIM;
        combine_weights<<<(tot + 255) / 256, 256>>>(W1, b1, W2);
    }
    gemm_mma<<<(N + 127) / 128, 256>>>(N, features, WcH, X0);

    // ---- join ----
    cudaStreamWaitEvent(0, evCsr, 0);

    const int gthreads = 256;
    const int wpb = gthreads / 32;
    const int gblocks = (N + wpb - 1) / wpb;
    const float inv = 1.0f / PSCALE;   // 0.25

    // Ps = (prop(X0) + c)/4            [stored scale 4]
    gather64h<true><<<gblocks, gthreads>>>((const __half2*)X0, P, nullptr, C,
                                           N, inv, 0.0f, inv);
    // Hs = (prop(4*Ps) + b2)/16        [stored scale 16]
    gather64h<true><<<gblocks, gthreads>>>((const __half2*)P, H, nullptr, b2,
                                           N, inv, 0.0f, inv * inv);

    // ---- APPNP: y_{k+1} = (0.9/4)*prop(y_k) + (0.1/4^{k+1})*Hs ----
    const __half* xcur = H;
    float hscale = ALPHA_F;
    for (int k = 0; k < K_STEPS; k++) {
        if (k == K_STEPS - 1) {
            const float wfin = (1.0f - ALPHA_F) * 16.0f * 262144.0f;  // 0.9*16*4^9
            const float afin = ALPHA_F * 16.0f;                        // 1.6
            gather64h<false><<<gblocks, gthreads>>>((const __half2*)xcur, out,
                                                    (const __half2*)H, nullptr,
                                                    N, wfin, afin, 0.0f);
        } else {
            hscale *= inv;
            __half* xnext = (k & 1) ? B : A;
            gather64h<true><<<gblocks, gthreads>>>((const __half2*)xcur, xnext,
                                                   (const __half2*)H, nullptr,
                                                   N, (1.0f - ALPHA_F) * inv, hscale, 0.0f);
            xcur = xnext;
        }
    }

    // tail (reference returns (x, 10); fill any extra outputs with 10)
    int tail = out_size - N * OUT_DIM;
    if (tail > 0)
        fill_tail<<<(tail + 255) / 256, 256>>>(out, N * OUT_DIM, out_size);
}